// round 6
// baseline (speedup 1.0000x reference)
#include <cuda_runtime.h>
#include <cuda_fp16.h>
#include <cstdint>

#define NB  8
#define NPT 1024
#define DD  512
#define NH  8
#define DH  64
#define MM  (NB * NPT)
#define SCALE 0.04419417382415922f   // 1/sqrt(512)

// ---------------- scratch (device globals; allocation-free) ----------------
__device__ float  g_q [(size_t)MM * DD];             // fp32 (exact residual)
__device__ float  g_qt[(size_t)MM * DD];             // tf32-rounded
__device__ float  g_k [(size_t)MM * DD];             // tf32-rounded
__device__ float  g_v [(size_t)MM * DD];             // tf32-rounded
__device__ float  g_o [(size_t)MM * DD];
__device__ __half g_A [(size_t)NH * NB * NPT * NPT]; // U = exp(s), fp16 (128 MB)
__device__ float  g_Z [(size_t)NH * NB * NPT];       // 1/rowsum

// ---------------- helpers ----------------
__device__ __forceinline__ uint32_t f2tf(float f) {
    uint32_t u;
    asm("cvt.rna.tf32.f32 %0, %1;" : "=r"(u) : "f"(f));
    return u;
}
__device__ __forceinline__ float f2tff(float f) {
    uint32_t u = f2tf(f);
    return __uint_as_float(u);
}
__device__ __forceinline__ void mma8(float* c, const uint32_t* a, const uint32_t* b) {
    asm volatile(
        "mma.sync.aligned.m16n8k8.row.col.f32.tf32.tf32.f32 "
        "{%0,%1,%2,%3},{%4,%5,%6,%7},{%8,%9},{%0,%1,%2,%3};"
        : "+f"(c[0]), "+f"(c[1]), "+f"(c[2]), "+f"(c[3])
        : "r"(a[0]), "r"(a[1]), "r"(a[2]), "r"(a[3]), "r"(b[0]), "r"(b[1]));
}
__device__ __forceinline__ void cpa16(uint32_t dst, const void* src) {
    asm volatile("cp.async.cg.shared.global [%0], [%1], 16;" :: "r"(dst), "l"(src));
}
#define CP_COMMIT() asm volatile("cp.async.commit_group;")
#define CP_WAIT(N)  asm volatile("cp.async.wait_group %0;" :: "n"(N))

// ======================================================================
// GEMM: C[M,512] = X[M,512] @ W[512,512] + b. Register-prefetch pipelined.
// EPI 0: C=XW+b fp32   EPI 1: C = X + relu(XW+b)
// EPI 2: C=tf32(XW+b)  EPI 3: C fp32, C2 tf32 copy
// ======================================================================
template <int EPI>
__global__ void __launch_bounds__(256) gemm512_tc(
    const float* __restrict__ X, const float* __restrict__ W,
    const float* __restrict__ bias, float* __restrict__ C, float* __restrict__ C2)
{
    __shared__ uint32_t Xs[128 * 36];   // stride 36 (mod 32 == 4)
    __shared__ uint32_t Ws[32 * 72];    // stride 72 (mod 32 == 8)
    const int tid = threadIdx.x, lane = tid & 31, w = tid >> 5;
    const int m0 = blockIdx.y << 7, n0 = blockIdx.x << 6;
    const int wm = (w & 3) << 5, wn = (w >> 2) << 5;

    float acc[2][4][4];
#pragma unroll
    for (int mf = 0; mf < 2; mf++)
#pragma unroll
        for (int nf = 0; nf < 4; nf++)
#pragma unroll
            for (int x = 0; x < 4; x++) acc[mf][nf][x] = 0.f;

    const int xr = tid >> 1, xcb = (tid & 1) << 4;
    const int wk = tid >> 3, wnn = (tid & 7) << 3;
    const float* xsrc = X + (size_t)(m0 + xr) * DD + xcb;
    const float* wsrc = W + (size_t)wk * DD + n0 + wnn;
    uint32_t* xdst = &Xs[xr * 36 + xcb];
    uint32_t* wdst = &Ws[wk * 72 + wnn];

    float4 xreg[4], wreg[2];
#pragma unroll
    for (int t = 0; t < 4; t++) xreg[t] = *(const float4*)(xsrc + 4 * t);
#pragma unroll
    for (int t = 0; t < 2; t++) wreg[t] = *(const float4*)(wsrc + 4 * t);

    for (int k0 = 0; k0 < DD; k0 += 32) {
#pragma unroll
        for (int t = 0; t < 4; t++) {
            xdst[4 * t + 0] = f2tf(xreg[t].x); xdst[4 * t + 1] = f2tf(xreg[t].y);
            xdst[4 * t + 2] = f2tf(xreg[t].z); xdst[4 * t + 3] = f2tf(xreg[t].w);
        }
#pragma unroll
        for (int t = 0; t < 2; t++) {
            wdst[4 * t + 0] = f2tf(wreg[t].x); wdst[4 * t + 1] = f2tf(wreg[t].y);
            wdst[4 * t + 2] = f2tf(wreg[t].z); wdst[4 * t + 3] = f2tf(wreg[t].w);
        }
        __syncthreads();
        if (k0 + 32 < DD) {
#pragma unroll
            for (int t = 0; t < 4; t++) xreg[t] = *(const float4*)(xsrc + k0 + 32 + 4 * t);
#pragma unroll
            for (int t = 0; t < 2; t++) wreg[t] = *(const float4*)(wsrc + (size_t)(k0 + 32) * DD + 4 * t);
        }
#pragma unroll
        for (int kk = 0; kk < 32; kk += 8) {
            uint32_t af[2][4], bf[4][2];
            const int c = kk + (lane & 3);
#pragma unroll
            for (int mf = 0; mf < 2; mf++) {
                int row = wm + (mf << 4) + (lane >> 2);
                af[mf][0] = Xs[row * 36 + c];
                af[mf][1] = Xs[(row + 8) * 36 + c];
                af[mf][2] = Xs[row * 36 + c + 4];
                af[mf][3] = Xs[(row + 8) * 36 + c + 4];
            }
#pragma unroll
            for (int nf = 0; nf < 4; nf++) {
                int cr = wn + (nf << 3) + (lane >> 2);
                bf[nf][0] = Ws[c * 72 + cr];
                bf[nf][1] = Ws[(c + 4) * 72 + cr];
            }
#pragma unroll
            for (int mf = 0; mf < 2; mf++)
#pragma unroll
                for (int nf = 0; nf < 4; nf++)
                    mma8(acc[mf][nf], af[mf], bf[nf]);
        }
        __syncthreads();
    }

#pragma unroll
    for (int mf = 0; mf < 2; mf++) {
        int row = m0 + wm + (mf << 4) + (lane >> 2);
#pragma unroll
        for (int nf = 0; nf < 4; nf++) {
            int col = n0 + wn + (nf << 3) + ((lane & 3) << 1);
            float2 bb = *(const float2*)(bias + col);
            float2 v0 = make_float2(acc[mf][nf][0] + bb.x, acc[mf][nf][1] + bb.y);
            float2 v1 = make_float2(acc[mf][nf][2] + bb.x, acc[mf][nf][3] + bb.y);
            if (EPI == 1) {
                float2 r0 = *(const float2*)(X + (size_t)row * DD + col);
                float2 r1 = *(const float2*)(X + (size_t)(row + 8) * DD + col);
                v0.x = r0.x + fmaxf(v0.x, 0.f); v0.y = r0.y + fmaxf(v0.y, 0.f);
                v1.x = r1.x + fmaxf(v1.x, 0.f); v1.y = r1.y + fmaxf(v1.y, 0.f);
            }
            if (EPI == 2) {
                v0.x = f2tff(v0.x); v0.y = f2tff(v0.y);
                v1.x = f2tff(v1.x); v1.y = f2tff(v1.y);
            }
            *(float2*)(C + (size_t)row * DD + col) = v0;
            *(float2*)(C + (size_t)(row + 8) * DD + col) = v1;
            if (EPI == 3) {
                float2 t0 = make_float2(f2tff(v0.x), f2tff(v0.y));
                float2 t1 = make_float2(f2tff(v1.x), f2tff(v1.y));
                *(float2*)(C2 + (size_t)row * DD + col) = t0;
                *(float2*)(C2 + (size_t)(row + 8) * DD + col) = t1;
            }
        }
    }
}

// ======================================================================
// Fused attention, cp.async double-buffered, j-chunk 64.
// smem words: Qs 128x68 | Ks[2] 64x68 | Vs[2] 64x72 | Ps 128x68 | zbuf 512 | invZ 128
// 512 threads = 16 warps, wM 4 x wN 4; warp tiles: S 32x16, PV 32x16.
// ======================================================================
#define QS_OFF 0
#define KS_OFF(bu) (8704 + (bu) * 4352)
#define VS_OFF(bu) (17408 + (bu) * 4608)
#define PS_OFF 26624
#define ZB_OFF 35328
#define IZ_OFF 35840
#define FUSED_SMEM_WORDS 35968
#define FUSED_SMEM_BYTES (FUSED_SMEM_WORDS * 4)

extern __shared__ uint32_t smw[];

__global__ void __launch_bounds__(512, 1) fused_attn()
{
    uint32_t* Qs = smw + QS_OFF;
    uint32_t* Ps = smw + PS_OFF;
    float* zbuf  = (float*)(smw + ZB_OFF);
    float* invZs = (float*)(smw + IZ_OFF);
    const uint32_t sbase = (uint32_t)__cvta_generic_to_shared(smw);

    const int tid = threadIdx.x, lane = tid & 31, w = tid >> 5;
    const int wM = w & 3, wN = w >> 2;
    const int hb = blockIdx.y, h = hb >> 3, b = hb & 7;
    const int i0 = blockIdx.x << 7;

    // cp.async Q tile (128x64, pre-rounded tf32) — 4 x 16B per thread
    {
        const float* src = g_qt + (size_t)(b * NPT + i0) * DD + h * DH;
#pragma unroll
        for (int t = 0; t < 4; t++) {
            int c = tid + (t << 9);
            int r = c >> 4, k4 = (c & 15) << 2;
            cpa16(sbase + (QS_OFF + r * 68 + k4) * 4, src + (size_t)r * DD + k4);
        }
        CP_COMMIT();
    }
    // cp.async K/V chunk 0 — 2 x 16B each per thread
    const float* kbase = g_k + (size_t)(b * NPT) * DD + h * DH;
    const float* vbase = g_v + (size_t)(b * NPT) * DD + h * DH;
#pragma unroll
    for (int t = 0; t < 2; t++) {
        int c = tid + (t << 9);
        int r = c >> 4, k4 = (c & 15) << 2;
        cpa16(sbase + (KS_OFF(0) + r * 68 + k4) * 4, kbase + (size_t)r * DD + k4);
        cpa16(sbase + (VS_OFF(0) + r * 72 + k4) * 4, vbase + (size_t)r * DD + k4);
    }
    CP_COMMIT();

    float oacc[2][2][4];
#pragma unroll
    for (int mf = 0; mf < 2; mf++)
#pragma unroll
        for (int nf = 0; nf < 2; nf++)
#pragma unroll
            for (int x = 0; x < 4; x++) oacc[mf][nf][x] = 0.f;
    float zl[4] = {0.f, 0.f, 0.f, 0.f};

    __half2* Aout = (__half2*)(g_A + (size_t)hb * NPT * NPT);

    for (int it = 0; it < 16; it++) {
        const int cur = it & 1;
        const uint32_t* Ks = smw + KS_OFF(cur);
        const uint32_t* Vs = smw + VS_OFF(cur);
        const int j0 = it << 6;

        CP_WAIT(0);
        __syncthreads();   // buffer visible to all; all done with prev iter's smem

        if (it + 1 < 16) {
            const int nb = cur ^ 1;
            const float* kc = kbase + (size_t)(j0 + 64) * DD;
            const float* vc = vbase + (size_t)(j0 + 64) * DD;
#pragma unroll
            for (int t = 0; t < 2; t++) {
                int c = tid + (t << 9);
                int r = c >> 4, k4 = (c & 15) << 2;
                cpa16(sbase + (KS_OFF(nb) + r * 68 + k4) * 4, kc + (size_t)r * DD + k4);
                cpa16(sbase + (VS_OFF(nb) + r * 72 + k4) * 4, vc + (size_t)r * DD + k4);
            }
            CP_COMMIT();
        }

        // ---- S = Q.K^T : warp tile 32(i) x 16(j), K=64 ----
        float sacc[2][2][4];
#pragma unroll
        for (int mf = 0; mf < 2; mf++)
#pragma unroll
            for (int nf = 0; nf < 2; nf++)
#pragma unroll
                for (int x = 0; x < 4; x++) sacc[mf][nf][x] = 0.f;

#pragma unroll
        for (int kk = 0; kk < 64; kk += 8) {
            uint32_t af[2][4], bf[2][2];
            const int c = kk + (lane & 3);
#pragma unroll
            for (int mf = 0; mf < 2; mf++) {
                int row = (wM << 5) + (mf << 4) + (lane >> 2);
                af[mf][0] = Qs[row * 68 + c];
                af[mf][1] = Qs[(row + 8) * 68 + c];
                af[mf][2] = Qs[row * 68 + c + 4];
                af[mf][3] = Qs[(row + 8) * 68 + c + 4];
            }
#pragma unroll
            for (int nf = 0; nf < 2; nf++) {
                int cr = (wN << 4) + (nf << 3) + (lane >> 2);
                bf[nf][0] = Ks[cr * 68 + c];
                bf[nf][1] = Ks[cr * 68 + c + 4];
            }
#pragma unroll
            for (int mf = 0; mf < 2; mf++)
#pragma unroll
                for (int nf = 0; nf < 2; nf++)
                    mma8(sacc[mf][nf], af[mf], bf[nf]);
        }

        // ---- exp, Z accum, P -> smem (tf32) + U -> g_A (fp16) ----
#pragma unroll
        for (int mf = 0; mf < 2; mf++) {
            int row = (wM << 5) + (mf << 4) + (lane >> 2);
#pragma unroll
            for (int nf = 0; nf < 2; nf++) {
                int col = (wN << 4) + (nf << 3) + ((lane & 3) << 1);
                float p0 = __expf(sacc[mf][nf][0] * SCALE);
                float p1 = __expf(sacc[mf][nf][1] * SCALE);
                float p2 = __expf(sacc[mf][nf][2] * SCALE);
                float p3 = __expf(sacc[mf][nf][3] * SCALE);
                zl[mf * 2 + 0] += p0 + p1;
                zl[mf * 2 + 1] += p2 + p3;
                Ps[row * 68 + col]           = f2tf(p0);
                Ps[row * 68 + col + 1]       = f2tf(p1);
                Ps[(row + 8) * 68 + col]     = f2tf(p2);
                Ps[(row + 8) * 68 + col + 1] = f2tf(p3);
                Aout[(size_t)(i0 + row) * (NPT >> 1) + ((j0 + col) >> 1)] =
                    __floats2half2_rn(p0, p1);
                Aout[(size_t)(i0 + row + 8) * (NPT >> 1) + ((j0 + col) >> 1)] =
                    __floats2half2_rn(p2, p3);
            }
        }
        __syncthreads();

        // ---- O += P.V : warp tile 32(i) x 16(d), K=64 ----
#pragma unroll
        for (int kk = 0; kk < 64; kk += 8) {
            uint32_t af[2][4], bf2[2][2];
            const int c = kk + (lane & 3);
#pragma unroll
            for (int mf = 0; mf < 2; mf++) {
                int row = (wM << 5) + (mf << 4) + (lane >> 2);
                af[mf][0] = Ps[row * 68 + c];
                af[mf][1] = Ps[(row + 8) * 68 + c];
                af[mf][2] = Ps[row * 68 + c + 4];
                af[mf][3] = Ps[(row + 8) * 68 + c + 4];
            }
#pragma unroll
            for (int nf = 0; nf < 2; nf++) {
                int cr = (wN << 4) + (nf << 3) + (lane >> 2);
                bf2[nf][0] = Vs[c * 72 + cr];
                bf2[nf][1] = Vs[(c + 4) * 72 + cr];
            }
#pragma unroll
            for (int mf = 0; mf < 2; mf++)
#pragma unroll
                for (int nf = 0; nf < 2; nf++)
                    mma8(oacc[mf][nf], af[mf], bf2[nf]);
        }
    }

    // ---- Z reduce ----
#pragma unroll
    for (int zi = 0; zi < 4; zi++) {
        zl[zi] += __shfl_xor_sync(0xffffffffu, zl[zi], 1);
        zl[zi] += __shfl_xor_sync(0xffffffffu, zl[zi], 2);
    }
    __syncthreads();
    if ((lane & 3) == 0) {
#pragma unroll
        for (int zi = 0; zi < 4; zi++) {
            int r = (wM << 5) + ((zi >> 1) << 4) + ((zi & 1) << 3) + (lane >> 2);
            zbuf[wN * 128 + r] = zl[zi];
        }
    }
    __syncthreads();
    if (tid < 128) {
        float Z = zbuf[tid] + zbuf[128 + tid] + zbuf[256 + tid] + zbuf[384 + tid];
        float iz = 1.0f / Z;
        invZs[tid] = iz;
        g_Z[(size_t)hb * NPT + i0 + tid] = iz;
    }
    __syncthreads();

    // ---- epilogue: O = q + O/Z (exact fp32 residual) ----
#pragma unroll
    for (int mf = 0; mf < 2; mf++) {
        int row = (wM << 5) + (mf << 4) + (lane >> 2);
        float iz0 = invZs[row], iz1 = invZs[row + 8];
#pragma unroll
        for (int nf = 0; nf < 2; nf++) {
            int cd = (wN << 4) + (nf << 3) + ((lane & 3) << 1);
            size_t gi0 = (size_t)(b * NPT + i0 + row) * DD + h * DH + cd;
            size_t gi1 = gi0 + (size_t)8 * DD;
            float2 q0 = *(const float2*)(g_q + gi0);
            float2 q1 = *(const float2*)(g_q + gi1);
            float2 o0 = make_float2(q0.x + oacc[mf][nf][0] * iz0,
                                    q0.y + oacc[mf][nf][1] * iz0);
            float2 o1 = make_float2(q1.x + oacc[mf][nf][2] * iz1,
                                    q1.y + oacc[mf][nf][3] * iz1);
            *(float2*)(g_o + gi0) = o0;
            *(float2*)(g_o + gi1) = o1;
        }
    }
}

// ======================================================================
// Am[b, j, i] = (1/8) * sum_h U[h,b,i,j] * invZ[h,b,i]   (half2 reads)
// grid (32 i-tiles, 16 j-tiles, 8 b), 256 threads. Tile 32(i) x 64(j).
// ======================================================================
__global__ void __launch_bounds__(256) meanA_kernel(float* __restrict__ out)
{
    __shared__ float s[64][33];
    __shared__ float ziv[8][32];
    const int b  = blockIdx.z;
    const int i0 = blockIdx.x << 5;
    const int j0 = blockIdx.y << 6;
    const int tx = threadIdx.x & 31;
    const int ty = threadIdx.x >> 5;   // 0..7

    ziv[ty][tx] = g_Z[(size_t)(ty * NB + b) * NPT + i0 + tx];
    __syncthreads();

    float2 acc[4];
#pragma unroll
    for (int r = 0; r < 4; r++) acc[r] = make_float2(0.f, 0.f);

#pragma unroll
    for (int h = 0; h < 8; h++) {
        const __half2* base = (const __half2*)(
            g_A + ((size_t)(h * NB + b) * NPT + i0) * NPT + j0);
#pragma unroll
        for (int r = 0; r < 4; r++) {
            int ii = ty + (r << 3);
            float2 f = __half22float2(base[(size_t)ii * (NPT >> 1) + tx]);
            float z = ziv[h][ii];
            acc[r].x += f.x * z;
            acc[r].y += f.y * z;
        }
    }
#pragma unroll
    for (int r = 0; r < 4; r++) {
        int ii = ty + (r << 3);
        s[2 * tx][ii]     = acc[r].x * 0.125f;
        s[2 * tx + 1][ii] = acc[r].y * 0.125f;
    }
    __syncthreads();

    float* ob = out + ((size_t)b * NPT + j0) * NPT + i0;
#pragma unroll
    for (int rr = 0; rr < 8; rr++) {
        int jj = ty + (rr << 3);
        ob[(size_t)jj * NPT + tx] = s[jj][tx];
    }
}

// ======================================================================
// Launch
// ======================================================================
extern "C" void kernel_launch(void* const* d_in, const int* in_sizes, int n_in,
                              void* d_out, int out_size)
{
    const float* Q  = (const float*)d_in[0];
    const float* K  = (const float*)d_in[1];
    const float* Wq = (const float*)d_in[2];
    const float* bq = (const float*)d_in[3];
    const float* Wk = (const float*)d_in[4];
    const float* bk = (const float*)d_in[5];
    const float* Wv = (const float*)d_in[6];
    const float* bv = (const float*)d_in[7];
    const float* Wo = (const float*)d_in[8];
    const float* bo = (const float*)d_in[9];
    float* out = (float*)d_out;

    static float *pq = nullptr, *pqt = nullptr, *pk = nullptr, *pv = nullptr, *po = nullptr;
    if (!pq) {
        void* t;
        cudaGetSymbolAddress(&t, g_q);  pq  = (float*)t;
        cudaGetSymbolAddress(&t, g_qt); pqt = (float*)t;
        cudaGetSymbolAddress(&t, g_k);  pk  = (float*)t;
        cudaGetSymbolAddress(&t, g_v);  pv  = (float*)t;
        cudaGetSymbolAddress(&t, g_o);  po  = (float*)t;
        cudaFuncSetAttribute(fused_attn, cudaFuncAttributeMaxDynamicSharedMemorySize,
                             FUSED_SMEM_BYTES);
    }

    dim3 ggemm(DD / 64, MM / 128);                    // (8, 64)

    gemm512_tc<3><<<ggemm, 256>>>(Q, Wq, bq, pq, pqt);
    gemm512_tc<2><<<ggemm, 256>>>(K, Wk, bk, pk, nullptr);
    gemm512_tc<2><<<ggemm, 256>>>(K, Wv, bv, pv, nullptr);

    fused_attn<<<dim3(8, 64), 512, FUSED_SMEM_BYTES>>>();

    gemm512_tc<1><<<ggemm, 256>>>(po, Wo, bo, out, nullptr);
    meanA_kernel<<<dim3(32, 16, 8), 256>>>(out + (size_t)MM * DD);
}

// round 7
// speedup vs baseline: 1.1963x; 1.1963x over previous
#include <cuda_runtime.h>
#include <cuda_fp16.h>
#include <cstdint>

#define NB  8
#define NPT 1024
#define DD  512
#define NH  8
#define DH  64
#define MM  (NB * NPT)
#define SCALE 0.04419417382415922f   // 1/sqrt(512)

// ---------------- scratch (device globals; allocation-free) ----------------
__device__ float  g_q [(size_t)MM * DD];             // fp32 (exact residual)
__device__ float  g_qt[(size_t)MM * DD];             // tf32-rounded
__device__ float  g_k [(size_t)MM * DD];             // tf32-rounded
__device__ __half g_vh[(size_t)MM * DD];             // fp16 V
__device__ float  g_o [(size_t)MM * DD];
__device__ __half g_A [(size_t)NH * NB * NPT * NPT]; // U = exp(s), fp16
__device__ float  g_Z [(size_t)NH * NB * NPT];       // 1/rowsum

// ---------------- helpers ----------------
__device__ __forceinline__ uint32_t f2tf(float f) {
    uint32_t u;
    asm("cvt.rna.tf32.f32 %0, %1;" : "=r"(u) : "f"(f));
    return u;
}
__device__ __forceinline__ float f2tff(float f) {
    uint32_t u = f2tf(f);
    return __uint_as_float(u);
}
__device__ __forceinline__ void mma8(float* c, const uint32_t* a, const uint32_t* b) {
    asm volatile(
        "mma.sync.aligned.m16n8k8.row.col.f32.tf32.tf32.f32 "
        "{%0,%1,%2,%3},{%4,%5,%6,%7},{%8,%9},{%0,%1,%2,%3};"
        : "+f"(c[0]), "+f"(c[1]), "+f"(c[2]), "+f"(c[3])
        : "r"(a[0]), "r"(a[1]), "r"(a[2]), "r"(a[3]), "r"(b[0]), "r"(b[1]));
}
__device__ __forceinline__ void mma16h(float* c, uint32_t a0, uint32_t a1,
                                       uint32_t a2, uint32_t a3,
                                       uint32_t b0, uint32_t b1) {
    asm volatile(
        "mma.sync.aligned.m16n8k16.row.col.f32.f16.f16.f32 "
        "{%0,%1,%2,%3},{%4,%5,%6,%7},{%8,%9},{%0,%1,%2,%3};"
        : "+f"(c[0]), "+f"(c[1]), "+f"(c[2]), "+f"(c[3])
        : "r"(a0), "r"(a1), "r"(a2), "r"(a3), "r"(b0), "r"(b1));
}
__device__ __forceinline__ void ldmx2t(uint32_t& b0, uint32_t& b1, uint32_t addr) {
    asm volatile("ldmatrix.sync.aligned.m8n8.x2.trans.shared.b16 {%0,%1}, [%2];"
                 : "=r"(b0), "=r"(b1) : "r"(addr));
}
__device__ __forceinline__ void cpa16(uint32_t dst, const void* src) {
    asm volatile("cp.async.cg.shared.global [%0], [%1], 16;" :: "r"(dst), "l"(src));
}
#define CP_COMMIT() asm volatile("cp.async.commit_group;")
#define CP_WAIT(N)  asm volatile("cp.async.wait_group %0;" :: "n"(N))

// ======================================================================
// GEMM: C[M,512] = X[M,512] @ W[512,512] + b. (proven R5 structure)
// EPI 1: C = X + relu(XW+b) fp32    EPI 2: C = tf32(XW+b)
// EPI 3: C fp32 + C2 tf32 copy      EPI 4: C = fp16(XW+b)
// ======================================================================
template <int EPI>
__global__ void __launch_bounds__(256) gemm512_tc(
    const float* __restrict__ X, const float* __restrict__ W,
    const float* __restrict__ bias, float* __restrict__ C, float* __restrict__ C2)
{
    __shared__ uint32_t Xs[128 * 36];
    __shared__ uint32_t Ws[32 * 72];
    const int tid = threadIdx.x, lane = tid & 31, w = tid >> 5;
    const int m0 = blockIdx.y << 7, n0 = blockIdx.x << 6;
    const int wm = (w & 3) << 5, wn = (w >> 2) << 5;

    float acc[2][4][4];
#pragma unroll
    for (int mf = 0; mf < 2; mf++)
#pragma unroll
        for (int nf = 0; nf < 4; nf++)
#pragma unroll
            for (int x = 0; x < 4; x++) acc[mf][nf][x] = 0.f;

    const int xr = tid >> 1, xcb = (tid & 1) << 4;
    const int wk = tid >> 3, wnn = (tid & 7) << 3;
    const float* xsrc = X + (size_t)(m0 + xr) * DD + xcb;
    const float* wsrc = W + (size_t)wk * DD + n0 + wnn;
    uint32_t* xdst = &Xs[xr * 36 + xcb];
    uint32_t* wdst = &Ws[wk * 72 + wnn];

    float4 xreg[4], wreg[2];
#pragma unroll
    for (int t = 0; t < 4; t++) xreg[t] = *(const float4*)(xsrc + 4 * t);
#pragma unroll
    for (int t = 0; t < 2; t++) wreg[t] = *(const float4*)(wsrc + 4 * t);

    for (int k0 = 0; k0 < DD; k0 += 32) {
#pragma unroll
        for (int t = 0; t < 4; t++) {
            xdst[4 * t + 0] = f2tf(xreg[t].x); xdst[4 * t + 1] = f2tf(xreg[t].y);
            xdst[4 * t + 2] = f2tf(xreg[t].z); xdst[4 * t + 3] = f2tf(xreg[t].w);
        }
#pragma unroll
        for (int t = 0; t < 2; t++) {
            wdst[4 * t + 0] = f2tf(wreg[t].x); wdst[4 * t + 1] = f2tf(wreg[t].y);
            wdst[4 * t + 2] = f2tf(wreg[t].z); wdst[4 * t + 3] = f2tf(wreg[t].w);
        }
        __syncthreads();
        if (k0 + 32 < DD) {
#pragma unroll
            for (int t = 0; t < 4; t++) xreg[t] = *(const float4*)(xsrc + k0 + 32 + 4 * t);
#pragma unroll
            for (int t = 0; t < 2; t++) wreg[t] = *(const float4*)(wsrc + (size_t)(k0 + 32) * DD + 4 * t);
        }
#pragma unroll
        for (int kk = 0; kk < 32; kk += 8) {
            uint32_t af[2][4], bf[4][2];
            const int c = kk + (lane & 3);
#pragma unroll
            for (int mf = 0; mf < 2; mf++) {
                int row = wm + (mf << 4) + (lane >> 2);
                af[mf][0] = Xs[row * 36 + c];
                af[mf][1] = Xs[(row + 8) * 36 + c];
                af[mf][2] = Xs[row * 36 + c + 4];
                af[mf][3] = Xs[(row + 8) * 36 + c + 4];
            }
#pragma unroll
            for (int nf = 0; nf < 4; nf++) {
                int cr = wn + (nf << 3) + (lane >> 2);
                bf[nf][0] = Ws[c * 72 + cr];
                bf[nf][1] = Ws[(c + 4) * 72 + cr];
            }
#pragma unroll
            for (int mf = 0; mf < 2; mf++)
#pragma unroll
                for (int nf = 0; nf < 4; nf++)
                    mma8(acc[mf][nf], af[mf], bf[nf]);
        }
        __syncthreads();
    }

#pragma unroll
    for (int mf = 0; mf < 2; mf++) {
        int row = m0 + wm + (mf << 4) + (lane >> 2);
#pragma unroll
        for (int nf = 0; nf < 4; nf++) {
            int col = n0 + wn + (nf << 3) + ((lane & 3) << 1);
            float2 bb = *(const float2*)(bias + col);
            float2 v0 = make_float2(acc[mf][nf][0] + bb.x, acc[mf][nf][1] + bb.y);
            float2 v1 = make_float2(acc[mf][nf][2] + bb.x, acc[mf][nf][3] + bb.y);
            if (EPI == 1) {
                float2 r0 = *(const float2*)(X + (size_t)row * DD + col);
                float2 r1 = *(const float2*)(X + (size_t)(row + 8) * DD + col);
                v0.x = r0.x + fmaxf(v0.x, 0.f); v0.y = r0.y + fmaxf(v0.y, 0.f);
                v1.x = r1.x + fmaxf(v1.x, 0.f); v1.y = r1.y + fmaxf(v1.y, 0.f);
            }
            if (EPI == 2) {
                v0.x = f2tff(v0.x); v0.y = f2tff(v0.y);
                v1.x = f2tff(v1.x); v1.y = f2tff(v1.y);
            }
            if (EPI == 4) {
                __half2* Ch = (__half2*)C;
                Ch[(size_t)row * (DD / 2) + (col >> 1)]       = __floats2half2_rn(v0.x, v0.y);
                Ch[(size_t)(row + 8) * (DD / 2) + (col >> 1)] = __floats2half2_rn(v1.x, v1.y);
            } else {
                *(float2*)(C + (size_t)row * DD + col) = v0;
                *(float2*)(C + (size_t)(row + 8) * DD + col) = v1;
                if (EPI == 3) {
                    float2 t0 = make_float2(f2tff(v0.x), f2tff(v0.y));
                    float2 t1 = make_float2(f2tff(v1.x), f2tff(v1.y));
                    *(float2*)(C2 + (size_t)row * DD + col) = t0;
                    *(float2*)(C2 + (size_t)(row + 8) * DD + col) = t1;
                }
            }
        }
    }
}

// ======================================================================
// Fused attention v2: 8 warps x 16 i-rows, j-chunk 64, register-resident P.
// S tf32 (Q,K smem) -> exp in regs -> pack fp16 -> PV m16n8k16 (V via
// ldmatrix.trans). One __syncthreads per iter. Z warp-local.
// smem bytes: Qs 128x68x4 | Ks[2] 64x68x4 | Vs[2] 64x72x2  = 88064
// ======================================================================
#define QS_B 0
#define KS_B(bu) (34816 + (bu) * 17408)
#define VS_B(bu) (69632 + (bu) * 9216)
#define FUSED_SMEM_BYTES 88064

extern __shared__ uint32_t smw[];

__global__ void __launch_bounds__(256, 2) fused_attn()
{
    uint32_t* Qs = smw;   // word-indexed
    const uint32_t sbase = (uint32_t)__cvta_generic_to_shared(smw);

    const int tid = threadIdx.x, lane = tid & 31, wid = tid >> 5;
    const int hb = blockIdx.y, h = hb >> 3, b = hb & 7;
    const int i0 = blockIdx.x << 7;
    const int r = (wid << 4) + (lane >> 2);      // warp-local row (and r+8)

    // cp.async Q tile (128x64 tf32)
    {
        const float* src = g_qt + (size_t)(b * NPT + i0) * DD + h * DH;
#pragma unroll
        for (int t = 0; t < 8; t++) {
            int c = tid + (t << 8);
            int rr = c >> 4, k4 = (c & 15) << 2;
            cpa16(sbase + QS_B + (rr * 68 + k4) * 4, src + (size_t)rr * DD + k4);
        }
        CP_COMMIT();
    }
    const float*  kbase = g_k + (size_t)(b * NPT) * DD + h * DH;
    const __half* vbase = g_vh + (size_t)(b * NPT) * DD + h * DH;
    // chunk 0
#pragma unroll
    for (int t = 0; t < 4; t++) {
        int c = tid + (t << 8);
        int rr = c >> 4, k4 = (c & 15) << 2;
        cpa16(sbase + KS_B(0) + (rr * 68 + k4) * 4, kbase + (size_t)rr * DD + k4);
    }
#pragma unroll
    for (int t = 0; t < 2; t++) {
        int c = tid + (t << 8);
        int rr = c >> 3, o16 = (c & 7) << 4;
        cpa16(sbase + VS_B(0) + rr * 144 + o16, (const char*)(vbase + (size_t)rr * DD) + o16);
    }
    CP_COMMIT();

    float oacc[8][4];
#pragma unroll
    for (int nf = 0; nf < 8; nf++)
#pragma unroll
        for (int x = 0; x < 4; x++) oacc[nf][x] = 0.f;
    float zl0 = 0.f, zl1 = 0.f;

    __half2* Aout = (__half2*)(g_A + (size_t)hb * NPT * NPT);

    for (int it = 0; it < 16; it++) {
        const int cur = it & 1;
        const uint32_t* Ks = smw + (KS_B(cur) >> 2);
        const uint32_t vsb = sbase + VS_B(cur);
        const int j0 = it << 6;

        CP_WAIT(0);
        __syncthreads();

        if (it + 1 < 16) {
            const int nb = cur ^ 1;
            const float*  kc = kbase + (size_t)(j0 + 64) * DD;
            const __half* vc = vbase + (size_t)(j0 + 64) * DD;
#pragma unroll
            for (int t = 0; t < 4; t++) {
                int c = tid + (t << 8);
                int rr = c >> 4, k4 = (c & 15) << 2;
                cpa16(sbase + KS_B(nb) + (rr * 68 + k4) * 4, kc + (size_t)rr * DD + k4);
            }
#pragma unroll
            for (int t = 0; t < 2; t++) {
                int c = tid + (t << 8);
                int rr = c >> 3, o16 = (c & 7) << 4;
                cpa16(sbase + VS_B(nb) + rr * 144 + o16, (const char*)(vc + (size_t)rr * DD) + o16);
            }
            CP_COMMIT();
        }

        // ---- S = Q.K^T : warp tile 16(i) x 64(j), K=64 ----
        float sacc[8][4];
#pragma unroll
        for (int nf = 0; nf < 8; nf++)
#pragma unroll
            for (int x = 0; x < 4; x++) sacc[nf][x] = 0.f;

#pragma unroll
        for (int kk = 0; kk < 64; kk += 8) {
            const int c = kk + (lane & 3);
            uint32_t a0 = Qs[r * 68 + c];
            uint32_t a1 = Qs[(r + 8) * 68 + c];
            uint32_t a2 = Qs[r * 68 + c + 4];
            uint32_t a3 = Qs[(r + 8) * 68 + c + 4];
            uint32_t af[4] = {a0, a1, a2, a3};
#pragma unroll
            for (int nf = 0; nf < 8; nf++) {
                int cr = (nf << 3) + (lane >> 2);
                uint32_t bf[2] = {Ks[cr * 68 + c], Ks[cr * 68 + c + 4]};
                mma8(sacc[nf], af, bf);
            }
        }

        // ---- exp in regs, pack fp16 P, store U, accumulate Z ----
        uint32_t h2lo[8], h2hi[8];
#pragma unroll
        for (int nf = 0; nf < 8; nf++) {
            float p0 = __expf(sacc[nf][0] * SCALE);
            float p1 = __expf(sacc[nf][1] * SCALE);
            float p2 = __expf(sacc[nf][2] * SCALE);
            float p3 = __expf(sacc[nf][3] * SCALE);
            zl0 += p0 + p1;
            zl1 += p2 + p3;
            __half2 lo = __floats2half2_rn(p0, p1);
            __half2 hi = __floats2half2_rn(p2, p3);
            h2lo[nf] = *(uint32_t*)&lo;
            h2hi[nf] = *(uint32_t*)&hi;
            int col = j0 + (nf << 3) + ((lane & 3) << 1);
            Aout[(size_t)(i0 + r) * (NPT >> 1) + (col >> 1)]     = lo;
            Aout[(size_t)(i0 + r + 8) * (NPT >> 1) + (col >> 1)] = hi;
        }

        // ---- O += P.V : fp16 m16n8k16, V B-frags via ldmatrix.trans ----
#pragma unroll
        for (int ks = 0; ks < 4; ks++) {
            uint32_t a0 = h2lo[2 * ks], a1 = h2hi[2 * ks];
            uint32_t a2 = h2lo[2 * ks + 1], a3 = h2hi[2 * ks + 1];
            uint32_t rowaddr = vsb + ((ks << 4) + (lane & 15)) * 144;
#pragma unroll
            for (int nf = 0; nf < 8; nf++) {
                uint32_t b0, b1;
                ldmx2t(b0, b1, rowaddr + (nf << 4));
                mma16h(oacc[nf], a0, a1, a2, a3, b0, b1);
            }
        }
    }

    // ---- Z: quad-local reduce (rows are warp-private) ----
    zl0 += __shfl_xor_sync(0xffffffffu, zl0, 1);
    zl0 += __shfl_xor_sync(0xffffffffu, zl0, 2);
    zl1 += __shfl_xor_sync(0xffffffffu, zl1, 1);
    zl1 += __shfl_xor_sync(0xffffffffu, zl1, 2);
    float iz0 = 1.0f / zl0, iz1 = 1.0f / zl1;
    if ((lane & 3) == 0) {
        g_Z[(size_t)hb * NPT + i0 + r]     = iz0;
        g_Z[(size_t)hb * NPT + i0 + r + 8] = iz1;
    }

    // ---- epilogue: O = q + O/Z (exact fp32 residual) ----
#pragma unroll
    for (int nf = 0; nf < 8; nf++) {
        int d = (nf << 3) + ((lane & 3) << 1);
        size_t gi0 = (size_t)(b * NPT + i0 + r) * DD + h * DH + d;
        size_t gi1 = gi0 + (size_t)8 * DD;
        float2 q0 = *(const float2*)(g_q + gi0);
        float2 q1 = *(const float2*)(g_q + gi1);
        float2 o0 = make_float2(q0.x + oacc[nf][0] * iz0, q0.y + oacc[nf][1] * iz0);
        float2 o1 = make_float2(q1.x + oacc[nf][2] * iz1, q1.y + oacc[nf][3] * iz1);
        *(float2*)(g_o + gi0) = o0;
        *(float2*)(g_o + gi1) = o1;
    }
}

// ======================================================================
// Am[b, j, i] = (1/8) * sum_h U[h,b,i,j] * invZ[h,b,i]   (half2 reads)
// ======================================================================
__global__ void __launch_bounds__(256) meanA_kernel(float* __restrict__ out)
{
    __shared__ float s[64][33];
    __shared__ float ziv[8][32];
    const int b  = blockIdx.z;
    const int i0 = blockIdx.x << 5;
    const int j0 = blockIdx.y << 6;
    const int tx = threadIdx.x & 31;
    const int ty = threadIdx.x >> 5;

    ziv[ty][tx] = g_Z[(size_t)(ty * NB + b) * NPT + i0 + tx];
    __syncthreads();

    float2 acc[4];
#pragma unroll
    for (int r = 0; r < 4; r++) acc[r] = make_float2(0.f, 0.f);

#pragma unroll
    for (int h = 0; h < 8; h++) {
        const __half2* base = (const __half2*)(
            g_A + ((size_t)(h * NB + b) * NPT + i0) * NPT + j0);
#pragma unroll
        for (int r = 0; r < 4; r++) {
            int ii = ty + (r << 3);
            float2 f = __half22float2(base[(size_t)ii * (NPT >> 1) + tx]);
            float z = ziv[h][ii];
            acc[r].x += f.x * z;
            acc[r].y += f.y * z;
        }
    }
#pragma unroll
    for (int r = 0; r < 4; r++) {
        int ii = ty + (r << 3);
        s[2 * tx][ii]     = acc[r].x * 0.125f;
        s[2 * tx + 1][ii] = acc[r].y * 0.125f;
    }
    __syncthreads();

    float* ob = out + ((size_t)b * NPT + j0) * NPT + i0;
#pragma unroll
    for (int rr = 0; rr < 8; rr++) {
        int jj = ty + (rr << 3);
        ob[(size_t)jj * NPT + tx] = s[jj][tx];
    }
}

// ======================================================================
// Launch
// ======================================================================
extern "C" void kernel_launch(void* const* d_in, const int* in_sizes, int n_in,
                              void* d_out, int out_size)
{
    const float* Q  = (const float*)d_in[0];
    const float* K  = (const float*)d_in[1];
    const float* Wq = (const float*)d_in[2];
    const float* bq = (const float*)d_in[3];
    const float* Wk = (const float*)d_in[4];
    const float* bk = (const float*)d_in[5];
    const float* Wv = (const float*)d_in[6];
    const float* bv = (const float*)d_in[7];
    const float* Wo = (const float*)d_in[8];
    const float* bo = (const float*)d_in[9];
    float* out = (float*)d_out;

    static float *pq = nullptr, *pqt = nullptr, *pk = nullptr, *po = nullptr, *pvh = nullptr;
    if (!pq) {
        void* t;
        cudaGetSymbolAddress(&t, g_q);  pq  = (float*)t;
        cudaGetSymbolAddress(&t, g_qt); pqt = (float*)t;
        cudaGetSymbolAddress(&t, g_k);  pk  = (float*)t;
        cudaGetSymbolAddress(&t, g_vh); pvh = (float*)t;
        cudaGetSymbolAddress(&t, g_o);  po  = (float*)t;
        cudaFuncSetAttribute(fused_attn, cudaFuncAttributeMaxDynamicSharedMemorySize,
                             FUSED_SMEM_BYTES);
    }

    dim3 ggemm(DD / 64, MM / 128);                    // (8, 64)

    gemm512_tc<3><<<ggemm, 256>>>(Q, Wq, bq, pq, pqt);
    gemm512_tc<2><<<ggemm, 256>>>(K, Wk, bk, pk, nullptr);
    gemm512_tc<4><<<ggemm, 256>>>(K, Wv, bv, pvh, nullptr);

    fused_attn<<<dim3(8, 64), 256, FUSED_SMEM_BYTES>>>();

    gemm512_tc<1><<<ggemm, 256>>>(po, Wo, bo, out, nullptr);
    meanA_kernel<<<dim3(32, 16, 8), 256>>>(out + (size_t)MM * DD);
}

// round 8
// speedup vs baseline: 1.3036x; 1.0896x over previous
#include <cuda_runtime.h>
#include <cuda_fp16.h>
#include <cstdint>

#define NB  8
#define NPT 1024
#define DD  512
#define NH  8
#define DH  64
#define MM  (NB * NPT)
#define SCALE 0.04419417382415922f   // 1/sqrt(512)

// ---------------- scratch (device globals; allocation-free) ----------------
__device__ float  g_q [(size_t)MM * DD];             // fp32 (exact residual)
__device__ __half g_qh[(size_t)MM * DD];             // fp16 q
__device__ __half g_kh[(size_t)MM * DD];             // fp16 k
__device__ __half g_vh[(size_t)MM * DD];             // fp16 v
__device__ float  g_o [(size_t)MM * DD];
__device__ __half g_A [(size_t)NH * NB * NPT * NPT]; // U = exp(s), fp16
__device__ float  g_Z [(size_t)NH * NB * NPT];       // 1/rowsum

// ---------------- helpers ----------------
__device__ __forceinline__ uint32_t f2tf(float f) {
    uint32_t u;
    asm("cvt.rna.tf32.f32 %0, %1;" : "=r"(u) : "f"(f));
    return u;
}
__device__ __forceinline__ void mma8(float* c, const uint32_t* a, const uint32_t* b) {
    asm volatile(
        "mma.sync.aligned.m16n8k8.row.col.f32.tf32.tf32.f32 "
        "{%0,%1,%2,%3},{%4,%5,%6,%7},{%8,%9},{%0,%1,%2,%3};"
        : "+f"(c[0]), "+f"(c[1]), "+f"(c[2]), "+f"(c[3])
        : "r"(a[0]), "r"(a[1]), "r"(a[2]), "r"(a[3]), "r"(b[0]), "r"(b[1]));
}
__device__ __forceinline__ void mma16h(float* c, uint32_t a0, uint32_t a1,
                                       uint32_t a2, uint32_t a3,
                                       uint32_t b0, uint32_t b1) {
    asm volatile(
        "mma.sync.aligned.m16n8k16.row.col.f32.f16.f16.f32 "
        "{%0,%1,%2,%3},{%4,%5,%6,%7},{%8,%9},{%0,%1,%2,%3};"
        : "+f"(c[0]), "+f"(c[1]), "+f"(c[2]), "+f"(c[3])
        : "r"(a0), "r"(a1), "r"(a2), "r"(a3), "r"(b0), "r"(b1));
}
__device__ __forceinline__ void ldmx4(uint32_t& a0, uint32_t& a1, uint32_t& a2,
                                      uint32_t& a3, uint32_t addr) {
    asm volatile("ldmatrix.sync.aligned.m8n8.x4.shared.b16 {%0,%1,%2,%3}, [%4];"
                 : "=r"(a0), "=r"(a1), "=r"(a2), "=r"(a3) : "r"(addr));
}
__device__ __forceinline__ void ldmx2(uint32_t& b0, uint32_t& b1, uint32_t addr) {
    asm volatile("ldmatrix.sync.aligned.m8n8.x2.shared.b16 {%0,%1}, [%2];"
                 : "=r"(b0), "=r"(b1) : "r"(addr));
}
__device__ __forceinline__ void ldmx2t(uint32_t& b0, uint32_t& b1, uint32_t addr) {
    asm volatile("ldmatrix.sync.aligned.m8n8.x2.trans.shared.b16 {%0,%1}, [%2];"
                 : "=r"(b0), "=r"(b1) : "r"(addr));
}
__device__ __forceinline__ void cpa16(uint32_t dst, const void* src) {
    asm volatile("cp.async.cg.shared.global [%0], [%1], 16;" :: "r"(dst), "l"(src));
}
#define CP_COMMIT() asm volatile("cp.async.commit_group;")
#define CP_WAIT(N)  asm volatile("cp.async.wait_group %0;" :: "n"(N))

// ======================================================================
// GEMM: C[M,512] = X[M,512] @ W[512,512] + b. (proven structure)
// EPI 1: C = X + relu(XW+b) fp32   EPI 4: C = fp16(XW+b)
// EPI 5: C fp32 + C2 fp16 copy
// ======================================================================
template <int EPI>
__global__ void __launch_bounds__(256) gemm512_tc(
    const float* __restrict__ X, const float* __restrict__ W,
    const float* __restrict__ bias, float* __restrict__ C, float* __restrict__ C2)
{
    __shared__ uint32_t Xs[128 * 36];
    __shared__ uint32_t Ws[32 * 72];
    const int tid = threadIdx.x, lane = tid & 31, w = tid >> 5;
    const int m0 = blockIdx.y << 7, n0 = blockIdx.x << 6;
    const int wm = (w & 3) << 5, wn = (w >> 2) << 5;

    float acc[2][4][4];
#pragma unroll
    for (int mf = 0; mf < 2; mf++)
#pragma unroll
        for (int nf = 0; nf < 4; nf++)
#pragma unroll
            for (int x = 0; x < 4; x++) acc[mf][nf][x] = 0.f;

    const int xr = tid >> 1, xcb = (tid & 1) << 4;
    const int wk = tid >> 3, wnn = (tid & 7) << 3;
    const float* xsrc = X + (size_t)(m0 + xr) * DD + xcb;
    const float* wsrc = W + (size_t)wk * DD + n0 + wnn;
    uint32_t* xdst = &Xs[xr * 36 + xcb];
    uint32_t* wdst = &Ws[wk * 72 + wnn];

    float4 xreg[4], wreg[2];
#pragma unroll
    for (int t = 0; t < 4; t++) xreg[t] = *(const float4*)(xsrc + 4 * t);
#pragma unroll
    for (int t = 0; t < 2; t++) wreg[t] = *(const float4*)(wsrc + 4 * t);

    for (int k0 = 0; k0 < DD; k0 += 32) {
#pragma unroll
        for (int t = 0; t < 4; t++) {
            xdst[4 * t + 0] = f2tf(xreg[t].x); xdst[4 * t + 1] = f2tf(xreg[t].y);
            xdst[4 * t + 2] = f2tf(xreg[t].z); xdst[4 * t + 3] = f2tf(xreg[t].w);
        }
#pragma unroll
        for (int t = 0; t < 2; t++) {
            wdst[4 * t + 0] = f2tf(wreg[t].x); wdst[4 * t + 1] = f2tf(wreg[t].y);
            wdst[4 * t + 2] = f2tf(wreg[t].z); wdst[4 * t + 3] = f2tf(wreg[t].w);
        }
        __syncthreads();
        if (k0 + 32 < DD) {
#pragma unroll
            for (int t = 0; t < 4; t++) xreg[t] = *(const float4*)(xsrc + k0 + 32 + 4 * t);
#pragma unroll
            for (int t = 0; t < 2; t++) wreg[t] = *(const float4*)(wsrc + (size_t)(k0 + 32) * DD + 4 * t);
        }
#pragma unroll
        for (int kk = 0; kk < 32; kk += 8) {
            uint32_t af[2][4], bf[4][2];
            const int c = kk + (lane & 3);
#pragma unroll
            for (int mf = 0; mf < 2; mf++) {
                int row = wm + (mf << 4) + (lane >> 2);
                af[mf][0] = Xs[row * 36 + c];
                af[mf][1] = Xs[(row + 8) * 36 + c];
                af[mf][2] = Xs[row * 36 + c + 4];
                af[mf][3] = Xs[(row + 8) * 36 + c + 4];
            }
#pragma unroll
            for (int nf = 0; nf < 4; nf++) {
                int cr = wn + (nf << 3) + (lane >> 2);
                bf[nf][0] = Ws[c * 72 + cr];
                bf[nf][1] = Ws[(c + 4) * 72 + cr];
            }
#pragma unroll
            for (int mf = 0; mf < 2; mf++)
#pragma unroll
                for (int nf = 0; nf < 4; nf++)
                    mma8(acc[mf][nf], af[mf], bf[nf]);
        }
        __syncthreads();
    }

#pragma unroll
    for (int mf = 0; mf < 2; mf++) {
        int row = m0 + wm + (mf << 4) + (lane >> 2);
#pragma unroll
        for (int nf = 0; nf < 4; nf++) {
            int col = n0 + wn + (nf << 3) + ((lane & 3) << 1);
            float2 bb = *(const float2*)(bias + col);
            float2 v0 = make_float2(acc[mf][nf][0] + bb.x, acc[mf][nf][1] + bb.y);
            float2 v1 = make_float2(acc[mf][nf][2] + bb.x, acc[mf][nf][3] + bb.y);
            if (EPI == 1) {
                float2 r0 = *(const float2*)(X + (size_t)row * DD + col);
                float2 r1 = *(const float2*)(X + (size_t)(row + 8) * DD + col);
                v0.x = r0.x + fmaxf(v0.x, 0.f); v0.y = r0.y + fmaxf(v0.y, 0.f);
                v1.x = r1.x + fmaxf(v1.x, 0.f); v1.y = r1.y + fmaxf(v1.y, 0.f);
            }
            if (EPI == 4) {
                __half2* Ch = (__half2*)C;
                Ch[(size_t)row * (DD / 2) + (col >> 1)]       = __floats2half2_rn(v0.x, v0.y);
                Ch[(size_t)(row + 8) * (DD / 2) + (col >> 1)] = __floats2half2_rn(v1.x, v1.y);
            } else {
                *(float2*)(C + (size_t)row * DD + col) = v0;
                *(float2*)(C + (size_t)(row + 8) * DD + col) = v1;
                if (EPI == 5) {
                    __half2* Ch = (__half2*)C2;
                    Ch[(size_t)row * (DD / 2) + (col >> 1)]       = __floats2half2_rn(v0.x, v0.y);
                    Ch[(size_t)(row + 8) * (DD / 2) + (col >> 1)] = __floats2half2_rn(v1.x, v1.y);
                }
            }
        }
    }
}

// ======================================================================
// Fused attention v3: all-fp16 MMA. 8 warps x 16 i-rows, j-chunk 64.
// Q A-frags hoisted out of j-loop (loop-invariant). S: m16n8k16 fp16,
// K via non-trans ldmatrix; PV: fp16, V via ldmatrix.trans.
// smem: Qs 128x(64+8)h | Ks[2] 64x72h | Vs[2] 64x72h  (rows 144B)
// ======================================================================
#define QS_B 0
#define KS_B(bu) (18432 + (bu) * 9216)
#define VS_B(bu) (36864 + (bu) * 9216)
#define FUSED_SMEM_BYTES 55296

extern __shared__ uint32_t smw[];

__global__ void __launch_bounds__(256, 2) fused_attn()
{
    const uint32_t sbase = (uint32_t)__cvta_generic_to_shared(smw);

    const int tid = threadIdx.x, lane = tid & 31, wid = tid >> 5;
    const int hb = blockIdx.y, h = hb >> 3, b = hb & 7;
    const int i0 = blockIdx.x << 7;
    const int r = (wid << 4) + (lane >> 2);      // warp rows r, r+8

    // cp.async Q tile (128 x 64 fp16)
    {
        const __half* src = g_qh + (size_t)(b * NPT + i0) * DD + h * DH;
#pragma unroll
        for (int t = 0; t < 4; t++) {
            int c = tid + (t << 8);
            int rr = c >> 3, seg = c & 7;
            cpa16(sbase + QS_B + rr * 144 + seg * 16,
                  (const char*)(src + (size_t)rr * DD) + seg * 16);
        }
        CP_COMMIT();
    }
    const __half* kbase = g_kh + (size_t)(b * NPT) * DD + h * DH;
    const __half* vbase = g_vh + (size_t)(b * NPT) * DD + h * DH;
    // chunk 0
#pragma unroll
    for (int t = 0; t < 2; t++) {
        int c = tid + (t << 8);
        int rr = c >> 3, seg = c & 7;
        cpa16(sbase + KS_B(0) + rr * 144 + seg * 16,
              (const char*)(kbase + (size_t)rr * DD) + seg * 16);
        cpa16(sbase + VS_B(0) + rr * 144 + seg * 16,
              (const char*)(vbase + (size_t)rr * DD) + seg * 16);
    }
    CP_COMMIT();

    // ---- hoist Q A-fragments (loop-invariant): 4 k-chunks x 4 regs ----
    uint32_t qf[4][4];
    CP_WAIT(1);
    __syncthreads();
    {
        const uint32_t qrow = (uint32_t)((wid << 4) + (lane & 7) + (((lane >> 3) & 1) << 3));
        const uint32_t koff = ((lane >> 4) & 1) << 4;   // +8 halves for groups 2,3
#pragma unroll
        for (int kc = 0; kc < 4; kc++)
            ldmx4(qf[kc][0], qf[kc][1], qf[kc][2], qf[kc][3],
                  sbase + QS_B + qrow * 144 + koff + kc * 32);
    }

    float oacc[8][4];
#pragma unroll
    for (int nf = 0; nf < 8; nf++)
#pragma unroll
        for (int x = 0; x < 4; x++) oacc[nf][x] = 0.f;
    float zl0 = 0.f, zl1 = 0.f;

    __half2* Aout = (__half2*)(g_A + (size_t)hb * NPT * NPT);

    for (int it = 0; it < 16; it++) {
        const int cur = it & 1;
        const uint32_t ksb = sbase + KS_B(cur);
        const uint32_t vsb = sbase + VS_B(cur);
        const int j0 = it << 6;

        CP_WAIT(0);
        __syncthreads();

        if (it + 1 < 16) {
            const int nb = cur ^ 1;
            const __half* kc = kbase + (size_t)(j0 + 64) * DD;
            const __half* vc = vbase + (size_t)(j0 + 64) * DD;
#pragma unroll
            for (int t = 0; t < 2; t++) {
                int c = tid + (t << 8);
                int rr = c >> 3, seg = c & 7;
                cpa16(sbase + KS_B(nb) + rr * 144 + seg * 16,
                      (const char*)(kc + (size_t)rr * DD) + seg * 16);
                cpa16(sbase + VS_B(nb) + rr * 144 + seg * 16,
                      (const char*)(vc + (size_t)rr * DD) + seg * 16);
            }
            CP_COMMIT();
        }

        // ---- interleaved S -> exp -> PV per ks (16 j-cols each) ----
        const uint32_t kboff = (((lane >> 3) & 1) << 4);   // +8 halves for matrix1
#pragma unroll
        for (int ks = 0; ks < 4; ks++) {
            uint32_t pe0, pe1, po0, po1;   // packed P: even nf (lo,hi), odd nf
#pragma unroll
            for (int t = 0; t < 2; t++) {
                const int nf = (ks << 1) + t;
                float s4[4] = {0.f, 0.f, 0.f, 0.f};
                uint32_t baddr = ksb + (uint32_t)((nf << 3) + (lane & 7)) * 144 + kboff;
#pragma unroll
                for (int kc = 0; kc < 4; kc++) {
                    uint32_t b0, b1;
                    ldmx2(b0, b1, baddr + kc * 32);
                    mma16h(s4, qf[kc][0], qf[kc][1], qf[kc][2], qf[kc][3], b0, b1);
                }
                float p0 = __expf(s4[0] * SCALE);
                float p1 = __expf(s4[1] * SCALE);
                float p2 = __expf(s4[2] * SCALE);
                float p3 = __expf(s4[3] * SCALE);
                zl0 += p0 + p1;
                zl1 += p2 + p3;
                __half2 lo = __floats2half2_rn(p0, p1);
                __half2 hi = __floats2half2_rn(p2, p3);
                int col = j0 + (nf << 3) + ((lane & 3) << 1);
                Aout[(size_t)(i0 + r) * (NPT >> 1) + (col >> 1)]     = lo;
                Aout[(size_t)(i0 + r + 8) * (NPT >> 1) + (col >> 1)] = hi;
                if (t == 0) { pe0 = *(uint32_t*)&lo; pe1 = *(uint32_t*)&hi; }
                else        { po0 = *(uint32_t*)&lo; po1 = *(uint32_t*)&hi; }
            }
            // PV for this ks: A = P cols j0+16ks..+15, B = V rows same
            uint32_t rowaddr = vsb + (uint32_t)((ks << 4) + (lane & 15)) * 144;
#pragma unroll
            for (int nf2 = 0; nf2 < 8; nf2++) {
                uint32_t b0, b1;
                ldmx2t(b0, b1, rowaddr + (nf2 << 4));
                mma16h(oacc[nf2], pe0, pe1, po0, po1, b0, b1);
            }
        }
    }

    // ---- Z: quad-local reduce (rows warp-private) ----
    zl0 += __shfl_xor_sync(0xffffffffu, zl0, 1);
    zl0 += __shfl_xor_sync(0xffffffffu, zl0, 2);
    zl1 += __shfl_xor_sync(0xffffffffu, zl1, 1);
    zl1 += __shfl_xor_sync(0xffffffffu, zl1, 2);
    float iz0 = 1.0f / zl0, iz1 = 1.0f / zl1;
    if ((lane & 3) == 0) {
        g_Z[(size_t)hb * NPT + i0 + r]     = iz0;
        g_Z[(size_t)hb * NPT + i0 + r + 8] = iz1;
    }

    // ---- epilogue: O = q + O/Z (exact fp32 residual) ----
#pragma unroll
    for (int nf = 0; nf < 8; nf++) {
        int d = (nf << 3) + ((lane & 3) << 1);
        size_t gi0 = (size_t)(b * NPT + i0 + r) * DD + h * DH + d;
        size_t gi1 = gi0 + (size_t)8 * DD;
        float2 q0 = *(const float2*)(g_q + gi0);
        float2 q1 = *(const float2*)(g_q + gi1);
        float2 o0 = make_float2(q0.x + oacc[nf][0] * iz0, q0.y + oacc[nf][1] * iz0);
        float2 o1 = make_float2(q1.x + oacc[nf][2] * iz1, q1.y + oacc[nf][3] * iz1);
        *(float2*)(g_o + gi0) = o0;
        *(float2*)(g_o + gi1) = o1;
    }
}

// ======================================================================
// Am[b, j, i] = (1/8) * sum_h U[h,b,i,j] * invZ[h,b,i]   (half2 reads)
// ======================================================================
__global__ void __launch_bounds__(256) meanA_kernel(float* __restrict__ out)
{
    __shared__ float s[64][33];
    __shared__ float ziv[8][32];
    const int b  = blockIdx.z;
    const int i0 = blockIdx.x << 5;
    const int j0 = blockIdx.y << 6;
    const int tx = threadIdx.x & 31;
    const int ty = threadIdx.x >> 5;

    ziv[ty][tx] = g_Z[(size_t)(ty * NB + b) * NPT + i0 + tx];
    __syncthreads();

    float2 acc[4];
#pragma unroll
    for (int r = 0; r < 4; r++) acc[r] = make_float2(0.f, 0.f);

#pragma unroll
    for (int h = 0; h < 8; h++) {
        const __half2* base = (const __half2*)(
            g_A + ((size_t)(h * NB + b) * NPT + i0) * NPT + j0);
#pragma unroll
        for (int r = 0; r < 4; r++) {
            int ii = ty + (r << 3);
            float2 f = __half22float2(base[(size_t)ii * (NPT >> 1) + tx]);
            float z = ziv[h][ii];
            acc[r].x += f.x * z;
            acc[r].y += f.y * z;
        }
    }
#pragma unroll
    for (int r = 0; r < 4; r++) {
        int ii = ty + (r << 3);
        s[2 * tx][ii]     = acc[r].x * 0.125f;
        s[2 * tx + 1][ii] = acc[r].y * 0.125f;
    }
    __syncthreads();

    float* ob = out + ((size_t)b * NPT + j0) * NPT + i0;
#pragma unroll
    for (int rr = 0; rr < 8; rr++) {
        int jj = ty + (rr << 3);
        ob[(size_t)jj * NPT + tx] = s[jj][tx];
    }
}

// ======================================================================
// Launch
// ======================================================================
extern "C" void kernel_launch(void* const* d_in, const int* in_sizes, int n_in,
                              void* d_out, int out_size)
{
    const float* Q  = (const float*)d_in[0];
    const float* K  = (const float*)d_in[1];
    const float* Wq = (const float*)d_in[2];
    const float* bq = (const float*)d_in[3];
    const float* Wk = (const float*)d_in[4];
    const float* bk = (const float*)d_in[5];
    const float* Wv = (const float*)d_in[6];
    const float* bv = (const float*)d_in[7];
    const float* Wo = (const float*)d_in[8];
    const float* bo = (const float*)d_in[9];
    float* out = (float*)d_out;

    static float *pq = nullptr, *pqh = nullptr, *pkh = nullptr, *pvh = nullptr, *po = nullptr;
    if (!pq) {
        void* t;
        cudaGetSymbolAddress(&t, g_q);  pq  = (float*)t;
        cudaGetSymbolAddress(&t, g_qh); pqh = (float*)t;
        cudaGetSymbolAddress(&t, g_kh); pkh = (float*)t;
        cudaGetSymbolAddress(&t, g_vh); pvh = (float*)t;
        cudaGetSymbolAddress(&t, g_o);  po  = (float*)t;
        cudaFuncSetAttribute(fused_attn, cudaFuncAttributeMaxDynamicSharedMemorySize,
                             FUSED_SMEM_BYTES);
    }

    dim3 ggemm(DD / 64, MM / 128);                    // (8, 64)

    gemm512_tc<5><<<ggemm, 256>>>(Q, Wq, bq, pq, pqh);
    gemm512_tc<4><<<ggemm, 256>>>(K, Wk, bk, pkh, nullptr);
    gemm512_tc<4><<<ggemm, 256>>>(K, Wv, bv, pvh, nullptr);

    fused_attn<<<dim3(8, 64), 256, FUSED_SMEM_BYTES>>>();

    gemm512_tc<1><<<ggemm, 256>>>(po, Wo, bo, out, nullptr);
    meanA_kernel<<<dim3(32, 16, 8), 256>>>(out + (size_t)MM * DD);
}

// round 9
// speedup vs baseline: 1.6175x; 1.2408x over previous
#include <cuda_runtime.h>
#include <cuda_fp16.h>
#include <cstdint>

#define NB  8
#define NPT 1024
#define DD  512
#define NH  8
#define DH  64
#define MM  (NB * NPT)
#define SCALE 0.04419417382415922f   // 1/sqrt(512)

// ---------------- scratch (device globals; allocation-free) ----------------
__device__ float  g_q [(size_t)MM * DD];             // fp32 (exact residual)
__device__ __half g_qh[(size_t)MM * DD];             // fp16 q
__device__ __half g_kh[(size_t)MM * DD];             // fp16 k
__device__ __half g_vh[(size_t)MM * DD];             // fp16 v
__device__ float  g_o [(size_t)MM * DD];
__device__ __half g_A [(size_t)NH * NB * NPT * NPT]; // U = exp(s), fp16
__device__ float  g_Z [(size_t)NH * NB * NPT];       // 1/rowsum

// ---------------- helpers ----------------
__device__ __forceinline__ void mma16h(float* c, uint32_t a0, uint32_t a1,
                                       uint32_t a2, uint32_t a3,
                                       uint32_t b0, uint32_t b1) {
    asm volatile(
        "mma.sync.aligned.m16n8k16.row.col.f32.f16.f16.f32 "
        "{%0,%1,%2,%3},{%4,%5,%6,%7},{%8,%9},{%0,%1,%2,%3};"
        : "+f"(c[0]), "+f"(c[1]), "+f"(c[2]), "+f"(c[3])
        : "r"(a0), "r"(a1), "r"(a2), "r"(a3), "r"(b0), "r"(b1));
}
__device__ __forceinline__ void ldmx4(uint32_t& a0, uint32_t& a1, uint32_t& a2,
                                      uint32_t& a3, uint32_t addr) {
    asm volatile("ldmatrix.sync.aligned.m8n8.x4.shared.b16 {%0,%1,%2,%3}, [%4];"
                 : "=r"(a0), "=r"(a1), "=r"(a2), "=r"(a3) : "r"(addr));
}
__device__ __forceinline__ void ldmx2(uint32_t& b0, uint32_t& b1, uint32_t addr) {
    asm volatile("ldmatrix.sync.aligned.m8n8.x2.shared.b16 {%0,%1}, [%2];"
                 : "=r"(b0), "=r"(b1) : "r"(addr));
}
__device__ __forceinline__ void ldmx2t(uint32_t& b0, uint32_t& b1, uint32_t addr) {
    asm volatile("ldmatrix.sync.aligned.m8n8.x2.trans.shared.b16 {%0,%1}, [%2];"
                 : "=r"(b0), "=r"(b1) : "r"(addr));
}
__device__ __forceinline__ void cpa16(uint32_t dst, const void* src) {
    asm volatile("cp.async.cg.shared.global [%0], [%1], 16;" :: "r"(dst), "l"(src));
}
#define CP_COMMIT() asm volatile("cp.async.commit_group;")
#define CP_WAIT(N)  asm volatile("cp.async.wait_group %0;" :: "n"(N))

// ======================================================================
// GEMM fp16-MMA: C[M,512] = X[M,512] @ W[512,512] + b.
// Block 128x64, K-chunk 32, 8 warps (M4 x N2), warp 32x32. fp16 in smem
// (144B padded rows, ldmatrix conflict-free), m16n8k16, fp32 accum.
// EPI 1: C = X + relu(XW+b) fp32   EPI 4: C = fp16(XW+b)
// EPI 5: C fp32 + C2 fp16 copy
// ======================================================================
template <int EPI>
__global__ void __launch_bounds__(256) gemm512_f16(
    const float* __restrict__ X, const float* __restrict__ W,
    const float* __restrict__ bias, float* __restrict__ C, float* __restrict__ C2)
{
    __shared__ __half Xs[128 * 72];   // 72 halves = 144B rows
    __shared__ __half Ws[32 * 72];
    const uint32_t xsb = (uint32_t)__cvta_generic_to_shared(Xs);
    const uint32_t wsb = (uint32_t)__cvta_generic_to_shared(Ws);

    const int tid = threadIdx.x, lane = tid & 31, w = tid >> 5;
    const int m0 = blockIdx.y << 7, n0 = blockIdx.x << 6;
    const int wm = (w & 3) << 5, wn = (w >> 2) << 5;

    float acc[2][4][4];
#pragma unroll
    for (int mf = 0; mf < 2; mf++)
#pragma unroll
        for (int nf = 0; nf < 4; nf++)
#pragma unroll
            for (int x = 0; x < 4; x++) acc[mf][nf][x] = 0.f;

    const int xr = tid >> 1, xcb = (tid & 1) << 4;     // row, half-offset (0/16)
    const int wk = tid >> 3, wnn = (tid & 7) << 3;     // row(k), half-offset
    const float* xsrc = X + (size_t)(m0 + xr) * DD + xcb;
    const float* wsrc = W + (size_t)wk * DD + n0 + wnn;
    __half2* xdst = (__half2*)(Xs + xr * 72 + xcb);
    __half2* wdst = (__half2*)(Ws + wk * 72 + wnn);

    float4 xreg[4], wreg[2];
#pragma unroll
    for (int t = 0; t < 4; t++) xreg[t] = *(const float4*)(xsrc + 4 * t);
#pragma unroll
    for (int t = 0; t < 2; t++) wreg[t] = *(const float4*)(wsrc + 4 * t);

    // fragment addresses (loop-invariant parts)
    const uint32_t arow = (uint32_t)((lane & 7) + (((lane >> 3) & 1) << 3));
    const uint32_t akoff = ((lane >> 4) & 1) << 4;      // bytes
    const uint32_t brow = (uint32_t)(lane & 15);

    for (int k0 = 0; k0 < DD; k0 += 32) {
#pragma unroll
        for (int t = 0; t < 4; t++) {
            xdst[2 * t]     = __floats2half2_rn(xreg[t].x, xreg[t].y);
            xdst[2 * t + 1] = __floats2half2_rn(xreg[t].z, xreg[t].w);
        }
#pragma unroll
        for (int t = 0; t < 2; t++) {
            wdst[2 * t]     = __floats2half2_rn(wreg[t].x, wreg[t].y);
            wdst[2 * t + 1] = __floats2half2_rn(wreg[t].z, wreg[t].w);
        }
        __syncthreads();
        if (k0 + 32 < DD) {
#pragma unroll
            for (int t = 0; t < 4; t++) xreg[t] = *(const float4*)(xsrc + k0 + 32 + 4 * t);
#pragma unroll
            for (int t = 0; t < 2; t++) wreg[t] = *(const float4*)(wsrc + (size_t)(k0 + 32) * DD + 4 * t);
        }
#pragma unroll
        for (int kc = 0; kc < 2; kc++) {
            uint32_t af[2][4];
#pragma unroll
            for (int mf = 0; mf < 2; mf++)
                ldmx4(af[mf][0], af[mf][1], af[mf][2], af[mf][3],
                      xsb + (uint32_t)(wm + (mf << 4) + arow) * 144 + akoff + kc * 32);
#pragma unroll
            for (int nf = 0; nf < 4; nf++) {
                uint32_t b0, b1;
                ldmx2t(b0, b1, wsb + ((kc << 4) + brow) * 144 + wn * 2 + (nf << 4));
#pragma unroll
                for (int mf = 0; mf < 2; mf++)
                    mma16h(acc[mf][nf], af[mf][0], af[mf][1], af[mf][2], af[mf][3], b0, b1);
            }
        }
        __syncthreads();
    }

#pragma unroll
    for (int mf = 0; mf < 2; mf++) {
        int row = m0 + wm + (mf << 4) + (lane >> 2);
#pragma unroll
        for (int nf = 0; nf < 4; nf++) {
            int col = n0 + wn + (nf << 3) + ((lane & 3) << 1);
            float2 bb = *(const float2*)(bias + col);
            float2 v0 = make_float2(acc[mf][nf][0] + bb.x, acc[mf][nf][1] + bb.y);
            float2 v1 = make_float2(acc[mf][nf][2] + bb.x, acc[mf][nf][3] + bb.y);
            if (EPI == 1) {
                float2 r0 = *(const float2*)(X + (size_t)row * DD + col);
                float2 r1 = *(const float2*)(X + (size_t)(row + 8) * DD + col);
                v0.x = r0.x + fmaxf(v0.x, 0.f); v0.y = r0.y + fmaxf(v0.y, 0.f);
                v1.x = r1.x + fmaxf(v1.x, 0.f); v1.y = r1.y + fmaxf(v1.y, 0.f);
            }
            if (EPI == 4) {
                __half2* Ch = (__half2*)C;
                Ch[(size_t)row * (DD / 2) + (col >> 1)]       = __floats2half2_rn(v0.x, v0.y);
                Ch[(size_t)(row + 8) * (DD / 2) + (col >> 1)] = __floats2half2_rn(v1.x, v1.y);
            } else {
                *(float2*)(C + (size_t)row * DD + col) = v0;
                *(float2*)(C + (size_t)(row + 8) * DD + col) = v1;
                if (EPI == 5) {
                    __half2* Ch = (__half2*)C2;
                    Ch[(size_t)row * (DD / 2) + (col >> 1)]       = __floats2half2_rn(v0.x, v0.y);
                    Ch[(size_t)(row + 8) * (DD / 2) + (col >> 1)] = __floats2half2_rn(v1.x, v1.y);
                }
            }
        }
    }
}

// ======================================================================
// Fused attention v3 (R7, proven): all-fp16 MMA. 8 warps x 16 i-rows,
// j-chunk 64, Q A-frags hoisted, register-resident P.
// ======================================================================
#define QS_B 0
#define KS_B(bu) (18432 + (bu) * 9216)
#define VS_B(bu) (36864 + (bu) * 9216)
#define FUSED_SMEM_BYTES 55296

extern __shared__ uint32_t smw[];

__global__ void __launch_bounds__(256, 2) fused_attn()
{
    const uint32_t sbase = (uint32_t)__cvta_generic_to_shared(smw);

    const int tid = threadIdx.x, lane = tid & 31, wid = tid >> 5;
    const int hb = blockIdx.y, h = hb >> 3, b = hb & 7;
    const int i0 = blockIdx.x << 7;
    const int r = (wid << 4) + (lane >> 2);

    {
        const __half* src = g_qh + (size_t)(b * NPT + i0) * DD + h * DH;
#pragma unroll
        for (int t = 0; t < 4; t++) {
            int c = tid + (t << 8);
            int rr = c >> 3, seg = c & 7;
            cpa16(sbase + QS_B + rr * 144 + seg * 16,
                  (const char*)(src + (size_t)rr * DD) + seg * 16);
        }
        CP_COMMIT();
    }
    const __half* kbase = g_kh + (size_t)(b * NPT) * DD + h * DH;
    const __half* vbase = g_vh + (size_t)(b * NPT) * DD + h * DH;
#pragma unroll
    for (int t = 0; t < 2; t++) {
        int c = tid + (t << 8);
        int rr = c >> 3, seg = c & 7;
        cpa16(sbase + KS_B(0) + rr * 144 + seg * 16,
              (const char*)(kbase + (size_t)rr * DD) + seg * 16);
        cpa16(sbase + VS_B(0) + rr * 144 + seg * 16,
              (const char*)(vbase + (size_t)rr * DD) + seg * 16);
    }
    CP_COMMIT();

    uint32_t qf[4][4];
    CP_WAIT(1);
    __syncthreads();
    {
        const uint32_t qrow = (uint32_t)((wid << 4) + (lane & 7) + (((lane >> 3) & 1) << 3));
        const uint32_t koff = ((lane >> 4) & 1) << 4;
#pragma unroll
        for (int kc = 0; kc < 4; kc++)
            ldmx4(qf[kc][0], qf[kc][1], qf[kc][2], qf[kc][3],
                  sbase + QS_B + qrow * 144 + koff + kc * 32);
    }

    float oacc[8][4];
#pragma unroll
    for (int nf = 0; nf < 8; nf++)
#pragma unroll
        for (int x = 0; x < 4; x++) oacc[nf][x] = 0.f;
    float zl0 = 0.f, zl1 = 0.f;

    __half2* Aout = (__half2*)(g_A + (size_t)hb * NPT * NPT);

    for (int it = 0; it < 16; it++) {
        const int cur = it & 1;
        const uint32_t ksb = sbase + KS_B(cur);
        const uint32_t vsb = sbase + VS_B(cur);
        const int j0 = it << 6;

        CP_WAIT(0);
        __syncthreads();

        if (it + 1 < 16) {
            const int nb = cur ^ 1;
            const __half* kc = kbase + (size_t)(j0 + 64) * DD;
            const __half* vc = vbase + (size_t)(j0 + 64) * DD;
#pragma unroll
            for (int t = 0; t < 2; t++) {
                int c = tid + (t << 8);
                int rr = c >> 3, seg = c & 7;
                cpa16(sbase + KS_B(nb) + rr * 144 + seg * 16,
                      (const char*)(kc + (size_t)rr * DD) + seg * 16);
                cpa16(sbase + VS_B(nb) + rr * 144 + seg * 16,
                      (const char*)(vc + (size_t)rr * DD) + seg * 16);
            }
            CP_COMMIT();
        }

        const uint32_t kboff = (((lane >> 3) & 1) << 4);
#pragma unroll
        for (int ks = 0; ks < 4; ks++) {
            uint32_t pe0, pe1, po0, po1;
#pragma unroll
            for (int t = 0; t < 2; t++) {
                const int nf = (ks << 1) + t;
                float s4[4] = {0.f, 0.f, 0.f, 0.f};
                uint32_t baddr = ksb + (uint32_t)((nf << 3) + (lane & 7)) * 144 + kboff;
#pragma unroll
                for (int kc = 0; kc < 4; kc++) {
                    uint32_t b0, b1;
                    ldmx2(b0, b1, baddr + kc * 32);
                    mma16h(s4, qf[kc][0], qf[kc][1], qf[kc][2], qf[kc][3], b0, b1);
                }
                float p0 = __expf(s4[0] * SCALE);
                float p1 = __expf(s4[1] * SCALE);
                float p2 = __expf(s4[2] * SCALE);
                float p3 = __expf(s4[3] * SCALE);
                zl0 += p0 + p1;
                zl1 += p2 + p3;
                __half2 lo = __floats2half2_rn(p0, p1);
                __half2 hi = __floats2half2_rn(p2, p3);
                int col = j0 + (nf << 3) + ((lane & 3) << 1);
                Aout[(size_t)(i0 + r) * (NPT >> 1) + (col >> 1)]     = lo;
                Aout[(size_t)(i0 + r + 8) * (NPT >> 1) + (col >> 1)] = hi;
                if (t == 0) { pe0 = *(uint32_t*)&lo; pe1 = *(uint32_t*)&hi; }
                else        { po0 = *(uint32_t*)&lo; po1 = *(uint32_t*)&hi; }
            }
            uint32_t rowaddr = vsb + (uint32_t)((ks << 4) + (lane & 15)) * 144;
#pragma unroll
            for (int nf2 = 0; nf2 < 8; nf2++) {
                uint32_t b0, b1;
                ldmx2t(b0, b1, rowaddr + (nf2 << 4));
                mma16h(oacc[nf2], pe0, pe1, po0, po1, b0, b1);
            }
        }
    }

    zl0 += __shfl_xor_sync(0xffffffffu, zl0, 1);
    zl0 += __shfl_xor_sync(0xffffffffu, zl0, 2);
    zl1 += __shfl_xor_sync(0xffffffffu, zl1, 1);
    zl1 += __shfl_xor_sync(0xffffffffu, zl1, 2);
    float iz0 = 1.0f / zl0, iz1 = 1.0f / zl1;
    if ((lane & 3) == 0) {
        g_Z[(size_t)hb * NPT + i0 + r]     = iz0;
        g_Z[(size_t)hb * NPT + i0 + r + 8] = iz1;
    }

#pragma unroll
    for (int nf = 0; nf < 8; nf++) {
        int d = (nf << 3) + ((lane & 3) << 1);
        size_t gi0 = (size_t)(b * NPT + i0 + r) * DD + h * DH + d;
        size_t gi1 = gi0 + (size_t)8 * DD;
        float2 q0 = *(const float2*)(g_q + gi0);
        float2 q1 = *(const float2*)(g_q + gi1);
        float2 o0 = make_float2(q0.x + oacc[nf][0] * iz0, q0.y + oacc[nf][1] * iz0);
        float2 o1 = make_float2(q1.x + oacc[nf][2] * iz1, q1.y + oacc[nf][3] * iz1);
        *(float2*)(g_o + gi0) = o0;
        *(float2*)(g_o + gi1) = o1;
    }
}

// ======================================================================
// Am[b, j, i] = (1/8) * sum_h U[h,b,i,j] * invZ[h,b,i]   (half2 reads)
// ======================================================================
__global__ void __launch_bounds__(256) meanA_kernel(float* __restrict__ out)
{
    __shared__ float s[64][33];
    __shared__ float ziv[8][32];
    const int b  = blockIdx.z;
    const int i0 = blockIdx.x << 5;
    const int j0 = blockIdx.y << 6;
    const int tx = threadIdx.x & 31;
    const int ty = threadIdx.x >> 5;

    ziv[ty][tx] = g_Z[(size_t)(ty * NB + b) * NPT + i0 + tx];
    __syncthreads();

    float2 acc[4];
#pragma unroll
    for (int r = 0; r < 4; r++) acc[r] = make_float2(0.f, 0.f);

#pragma unroll
    for (int h = 0; h < 8; h++) {
        const __half2* base = (const __half2*)(
            g_A + ((size_t)(h * NB + b) * NPT + i0) * NPT + j0);
#pragma unroll
        for (int r = 0; r < 4; r++) {
            int ii = ty + (r << 3);
            float2 f = __half22float2(base[(size_t)ii * (NPT >> 1) + tx]);
            float z = ziv[h][ii];
            acc[r].x += f.x * z;
            acc[r].y += f.y * z;
        }
    }
#pragma unroll
    for (int r = 0; r < 4; r++) {
        int ii = ty + (r << 3);
        s[2 * tx][ii]     = acc[r].x * 0.125f;
        s[2 * tx + 1][ii] = acc[r].y * 0.125f;
    }
    __syncthreads();

    float* ob = out + ((size_t)b * NPT + j0) * NPT + i0;
#pragma unroll
    for (int rr = 0; rr < 8; rr++) {
        int jj = ty + (rr << 3);
        ob[(size_t)jj * NPT + tx] = s[jj][tx];
    }
}

// ======================================================================
// Launch
// ======================================================================
extern "C" void kernel_launch(void* const* d_in, const int* in_sizes, int n_in,
                              void* d_out, int out_size)
{
    const float* Q  = (const float*)d_in[0];
    const float* K  = (const float*)d_in[1];
    const float* Wq = (const float*)d_in[2];
    const float* bq = (const float*)d_in[3];
    const float* Wk = (const float*)d_in[4];
    const float* bk = (const float*)d_in[5];
    const float* Wv = (const float*)d_in[6];
    const float* bv = (const float*)d_in[7];
    const float* Wo = (const float*)d_in[8];
    const float* bo = (const float*)d_in[9];
    float* out = (float*)d_out;

    static float *pq = nullptr, *pqh = nullptr, *pkh = nullptr, *pvh = nullptr, *po = nullptr;
    if (!pq) {
        void* t;
        cudaGetSymbolAddress(&t, g_q);  pq  = (float*)t;
        cudaGetSymbolAddress(&t, g_qh); pqh = (float*)t;
        cudaGetSymbolAddress(&t, g_kh); pkh = (float*)t;
        cudaGetSymbolAddress(&t, g_vh); pvh = (float*)t;
        cudaGetSymbolAddress(&t, g_o);  po  = (float*)t;
        cudaFuncSetAttribute(fused_attn, cudaFuncAttributeMaxDynamicSharedMemorySize,
                             FUSED_SMEM_BYTES);
    }

    dim3 ggemm(DD / 64, MM / 128);                    // (8, 64)

    gemm512_f16<5><<<ggemm, 256>>>(Q, Wq, bq, pq, pqh);
    gemm512_f16<4><<<ggemm, 256>>>(K, Wk, bk, pkh, nullptr);
    gemm512_f16<4><<<ggemm, 256>>>(K, Wv, bv, pvh, nullptr);

    fused_attn<<<dim3(8, 64), 256, FUSED_SMEM_BYTES>>>();

    gemm512_f16<1><<<ggemm, 256>>>(po, Wo, bo, out, nullptr);
    meanA_kernel<<<dim3(32, 16, 8), 256>>>(out + (size_t)MM * DD);
}

// round 10
// speedup vs baseline: 2.1080x; 1.3033x over previous
#include <cuda_runtime.h>
#include <cuda_fp16.h>
#include <cstdint>

#define NB  8
#define NPT 1024
#define DD  512
#define NH  8
#define DH  64
#define MM  (NB * NPT)
#define SCALE 0.04419417382415922f   // 1/sqrt(512)

// ---------------- scratch (device globals; allocation-free) ----------------
__device__ float  g_q  [(size_t)MM * DD];            // fp32 q (exact residual)
__device__ __half g_qh [(size_t)MM * DD];            // fp16 q
__device__ __half g_kh [(size_t)MM * DD];            // fp16 k
__device__ __half g_vh [(size_t)MM * DD];            // fp16 v
__device__ float  g_o  [(size_t)MM * DD];            // fp32 O (residual for out-proj)
__device__ __half g_oh [(size_t)MM * DD];            // fp16 O (mma operand)
__device__ __half g_Qin[(size_t)MM * DD];            // fp16 raw Q
__device__ __half g_Kin[(size_t)MM * DD];            // fp16 raw K
__device__ __half g_Wh [4][(size_t)DD * DD];         // fp16 Wq,Wk,Wv,Wo
__device__ __half g_A  [(size_t)NH * NB * NPT * NPT];// U = exp(s), fp16
__device__ float  g_Z  [(size_t)NH * NB * NPT];      // 1/rowsum

// ---------------- helpers ----------------
__device__ __forceinline__ void mma16h(float* c, uint32_t a0, uint32_t a1,
                                       uint32_t a2, uint32_t a3,
                                       uint32_t b0, uint32_t b1) {
    asm volatile(
        "mma.sync.aligned.m16n8k16.row.col.f32.f16.f16.f32 "
        "{%0,%1,%2,%3},{%4,%5,%6,%7},{%8,%9},{%0,%1,%2,%3};"
        : "+f"(c[0]), "+f"(c[1]), "+f"(c[2]), "+f"(c[3])
        : "r"(a0), "r"(a1), "r"(a2), "r"(a3), "r"(b0), "r"(b1));
}
__device__ __forceinline__ void ldmx4(uint32_t& a0, uint32_t& a1, uint32_t& a2,
                                      uint32_t& a3, uint32_t addr) {
    asm volatile("ldmatrix.sync.aligned.m8n8.x4.shared.b16 {%0,%1,%2,%3}, [%4];"
                 : "=r"(a0), "=r"(a1), "=r"(a2), "=r"(a3) : "r"(addr));
}
__device__ __forceinline__ void ldmx2(uint32_t& b0, uint32_t& b1, uint32_t addr) {
    asm volatile("ldmatrix.sync.aligned.m8n8.x2.shared.b16 {%0,%1}, [%2];"
                 : "=r"(b0), "=r"(b1) : "r"(addr));
}
__device__ __forceinline__ void ldmx2t(uint32_t& b0, uint32_t& b1, uint32_t addr) {
    asm volatile("ldmatrix.sync.aligned.m8n8.x2.trans.shared.b16 {%0,%1}, [%2];"
                 : "=r"(b0), "=r"(b1) : "r"(addr));
}
__device__ __forceinline__ void cpa16(uint32_t dst, const void* src) {
    asm volatile("cp.async.cg.shared.global [%0], [%1], 16;" :: "r"(dst), "l"(src));
}
#define CP_COMMIT() asm volatile("cp.async.commit_group;")
#define CP_WAIT(N)  asm volatile("cp.async.wait_group %0;" :: "n"(N))

// ======================================================================
// fp32 -> fp16 conversion passes (one-time, memory-bound)
// ======================================================================
__global__ void __launch_bounds__(256) cvt_qk(
    const float* __restrict__ Q, const float* __restrict__ K)
{
    const float4* src = (const float4*)(blockIdx.y ? K : Q);
    __half2* dst = (__half2*)(blockIdx.y ? g_Kin : g_Qin);
    int i = blockIdx.x * 256 + threadIdx.x;
#pragma unroll
    for (int t = 0; t < 4; t++) {
        int idx = i + t * (1024 * 256);
        float4 v = src[idx];
        dst[2 * idx]     = __floats2half2_rn(v.x, v.y);
        dst[2 * idx + 1] = __floats2half2_rn(v.z, v.w);
    }
}
__global__ void __launch_bounds__(256) cvt_w(
    const float* __restrict__ W0, const float* __restrict__ W1,
    const float* __restrict__ W2, const float* __restrict__ W3)
{
    const float* ws[4] = {W0, W1, W2, W3};
    const float4* src = (const float4*)ws[blockIdx.y];
    __half2* dst = (__half2*)g_Wh[blockIdx.y];
    int i = blockIdx.x * 256 + threadIdx.x;
#pragma unroll
    for (int t = 0; t < 4; t++) {
        int idx = i + t * (64 * 256);
        float4 v = src[idx];
        dst[2 * idx]     = __floats2half2_rn(v.x, v.y);
        dst[2 * idx + 1] = __floats2half2_rn(v.z, v.w);
    }
}

// ======================================================================
// GEMM v3: fp16 operands via cp.async double-buffer, K-chunk 64.
// Block 128x64, 8 warps (M4 x N2), warp 32x32, m16n8k16, fp32 accum.
// EPI 1: C = R + relu(XW+b) fp32 (R fp32 residual)
// EPI 4: C(half*) = fp16(XW+b)
// EPI 5: C fp32 + C2 fp16 copy
// smem bytes: Xs[2] 128x72h | Ws[2] 64x72h = 55296
// ======================================================================
#define GX_B(bu) ((bu) * 18432)
#define GW_B(bu) (36864 + (bu) * 9216)
#define GEMM_SMEM_BYTES 55296

extern __shared__ uint32_t gsm[];

template <int EPI>
__global__ void __launch_bounds__(256, 2) gemm512_h2(
    const __half* __restrict__ Xh, const __half* __restrict__ Wh,
    const float* __restrict__ bias, float* __restrict__ C,
    float* __restrict__ C2, const float* __restrict__ R)
{
    const uint32_t sbase = (uint32_t)__cvta_generic_to_shared(gsm);
    const int tid = threadIdx.x, lane = tid & 31, w = tid >> 5;
    const int m0 = blockIdx.y << 7, n0 = blockIdx.x << 6;
    const int wm = (w & 3) << 5, wn = (w >> 2) << 5;

    float acc[2][4][4];
#pragma unroll
    for (int mf = 0; mf < 2; mf++)
#pragma unroll
        for (int nf = 0; nf < 4; nf++)
#pragma unroll
            for (int x = 0; x < 4; x++) acc[mf][nf][x] = 0.f;

    // cp.async stage 0
    {
#pragma unroll
        for (int t = 0; t < 4; t++) {
            int c = tid + (t << 8);
            int rr = c >> 3, seg = c & 7;
            cpa16(sbase + GX_B(0) + rr * 144 + seg * 16,
                  (const char*)(Xh + (size_t)(m0 + rr) * DD) + seg * 16);
        }
#pragma unroll
        for (int t = 0; t < 2; t++) {
            int c = tid + (t << 8);
            int rr = c >> 3, seg = c & 7;
            cpa16(sbase + GW_B(0) + rr * 144 + seg * 16,
                  (const char*)(Wh + (size_t)rr * DD + n0) + seg * 16);
        }
        CP_COMMIT();
    }

    const uint32_t arow = (uint32_t)((lane & 7) + (((lane >> 3) & 1) << 3));
    const uint32_t akoff = ((lane >> 4) & 1) << 4;
    const uint32_t brow = (uint32_t)(lane & 15);

    for (int kc64 = 0; kc64 < 8; kc64++) {
        const int cur = kc64 & 1;
        const uint32_t xsb = sbase + GX_B(cur);
        const uint32_t wsb = sbase + GW_B(cur);

        CP_WAIT(0);
        __syncthreads();

        if (kc64 + 1 < 8) {
            const int nb = cur ^ 1;
            const int k0 = (kc64 + 1) << 6;
#pragma unroll
            for (int t = 0; t < 4; t++) {
                int c = tid + (t << 8);
                int rr = c >> 3, seg = c & 7;
                cpa16(sbase + GX_B(nb) + rr * 144 + seg * 16,
                      (const char*)(Xh + (size_t)(m0 + rr) * DD + k0) + seg * 16);
            }
#pragma unroll
            for (int t = 0; t < 2; t++) {
                int c = tid + (t << 8);
                int rr = c >> 3, seg = c & 7;
                cpa16(sbase + GW_B(nb) + rr * 144 + seg * 16,
                      (const char*)(Wh + (size_t)(k0 + rr) * DD + n0) + seg * 16);
            }
            CP_COMMIT();
        }

#pragma unroll
        for (int kc = 0; kc < 4; kc++) {
            uint32_t af[2][4];
#pragma unroll
            for (int mf = 0; mf < 2; mf++)
                ldmx4(af[mf][0], af[mf][1], af[mf][2], af[mf][3],
                      xsb + (uint32_t)(wm + (mf << 4) + arow) * 144 + akoff + kc * 32);
#pragma unroll
            for (int nf = 0; nf < 4; nf++) {
                uint32_t b0, b1;
                ldmx2t(b0, b1, wsb + ((kc << 4) + brow) * 144 + wn * 2 + (nf << 4));
#pragma unroll
                for (int mf = 0; mf < 2; mf++)
                    mma16h(acc[mf][nf], af[mf][0], af[mf][1], af[mf][2], af[mf][3], b0, b1);
            }
        }
    }

#pragma unroll
    for (int mf = 0; mf < 2; mf++) {
        int row = m0 + wm + (mf << 4) + (lane >> 2);
#pragma unroll
        for (int nf = 0; nf < 4; nf++) {
            int col = n0 + wn + (nf << 3) + ((lane & 3) << 1);
            float2 bb = *(const float2*)(bias + col);
            float2 v0 = make_float2(acc[mf][nf][0] + bb.x, acc[mf][nf][1] + bb.y);
            float2 v1 = make_float2(acc[mf][nf][2] + bb.x, acc[mf][nf][3] + bb.y);
            if (EPI == 1) {
                float2 r0 = *(const float2*)(R + (size_t)row * DD + col);
                float2 r1 = *(const float2*)(R + (size_t)(row + 8) * DD + col);
                v0.x = r0.x + fmaxf(v0.x, 0.f); v0.y = r0.y + fmaxf(v0.y, 0.f);
                v1.x = r1.x + fmaxf(v1.x, 0.f); v1.y = r1.y + fmaxf(v1.y, 0.f);
            }
            if (EPI == 4) {
                __half2* Ch = (__half2*)C;
                Ch[(size_t)row * (DD / 2) + (col >> 1)]       = __floats2half2_rn(v0.x, v0.y);
                Ch[(size_t)(row + 8) * (DD / 2) + (col >> 1)] = __floats2half2_rn(v1.x, v1.y);
            } else {
                *(float2*)(C + (size_t)row * DD + col) = v0;
                *(float2*)(C + (size_t)(row + 8) * DD + col) = v1;
                if (EPI == 5) {
                    __half2* Ch = (__half2*)C2;
                    Ch[(size_t)row * (DD / 2) + (col >> 1)]       = __floats2half2_rn(v0.x, v0.y);
                    Ch[(size_t)(row + 8) * (DD / 2) + (col >> 1)] = __floats2half2_rn(v1.x, v1.y);
                }
            }
        }
    }
}

// ======================================================================
// Fused attention (R7/R8 proven) + fp16 O copy in epilogue.
// ======================================================================
#define QS_B 0
#define KS_B(bu) (18432 + (bu) * 9216)
#define VS_B(bu) (36864 + (bu) * 9216)
#define FUSED_SMEM_BYTES 55296

extern __shared__ uint32_t smw[];

__global__ void __launch_bounds__(256, 2) fused_attn()
{
    const uint32_t sbase = (uint32_t)__cvta_generic_to_shared(smw);

    const int tid = threadIdx.x, lane = tid & 31, wid = tid >> 5;
    const int hb = blockIdx.y, h = hb >> 3, b = hb & 7;
    const int i0 = blockIdx.x << 7;
    const int r = (wid << 4) + (lane >> 2);

    {
        const __half* src = g_qh + (size_t)(b * NPT + i0) * DD + h * DH;
#pragma unroll
        for (int t = 0; t < 4; t++) {
            int c = tid + (t << 8);
            int rr = c >> 3, seg = c & 7;
            cpa16(sbase + QS_B + rr * 144 + seg * 16,
                  (const char*)(src + (size_t)rr * DD) + seg * 16);
        }
        CP_COMMIT();
    }
    const __half* kbase = g_kh + (size_t)(b * NPT) * DD + h * DH;
    const __half* vbase = g_vh + (size_t)(b * NPT) * DD + h * DH;
#pragma unroll
    for (int t = 0; t < 2; t++) {
        int c = tid + (t << 8);
        int rr = c >> 3, seg = c & 7;
        cpa16(sbase + KS_B(0) + rr * 144 + seg * 16,
              (const char*)(kbase + (size_t)rr * DD) + seg * 16);
        cpa16(sbase + VS_B(0) + rr * 144 + seg * 16,
              (const char*)(vbase + (size_t)rr * DD) + seg * 16);
    }
    CP_COMMIT();

    uint32_t qf[4][4];
    CP_WAIT(1);
    __syncthreads();
    {
        const uint32_t qrow = (uint32_t)((wid << 4) + (lane & 7) + (((lane >> 3) & 1) << 3));
        const uint32_t koff = ((lane >> 4) & 1) << 4;
#pragma unroll
        for (int kc = 0; kc < 4; kc++)
            ldmx4(qf[kc][0], qf[kc][1], qf[kc][2], qf[kc][3],
                  sbase + QS_B + qrow * 144 + koff + kc * 32);
    }

    float oacc[8][4];
#pragma unroll
    for (int nf = 0; nf < 8; nf++)
#pragma unroll
        for (int x = 0; x < 4; x++) oacc[nf][x] = 0.f;
    float zl0 = 0.f, zl1 = 0.f;

    __half2* Aout = (__half2*)(g_A + (size_t)hb * NPT * NPT);

    for (int it = 0; it < 16; it++) {
        const int cur = it & 1;
        const uint32_t ksb = sbase + KS_B(cur);
        const uint32_t vsb = sbase + VS_B(cur);
        const int j0 = it << 6;

        CP_WAIT(0);
        __syncthreads();

        if (it + 1 < 16) {
            const int nb = cur ^ 1;
            const __half* kc = kbase + (size_t)(j0 + 64) * DD;
            const __half* vc = vbase + (size_t)(j0 + 64) * DD;
#pragma unroll
            for (int t = 0; t < 2; t++) {
                int c = tid + (t << 8);
                int rr = c >> 3, seg = c & 7;
                cpa16(sbase + KS_B(nb) + rr * 144 + seg * 16,
                      (const char*)(kc + (size_t)rr * DD) + seg * 16);
                cpa16(sbase + VS_B(nb) + rr * 144 + seg * 16,
                      (const char*)(vc + (size_t)rr * DD) + seg * 16);
            }
            CP_COMMIT();
        }

        const uint32_t kboff = (((lane >> 3) & 1) << 4);
#pragma unroll
        for (int ks = 0; ks < 4; ks++) {
            uint32_t pe0, pe1, po0, po1;
#pragma unroll
            for (int t = 0; t < 2; t++) {
                const int nf = (ks << 1) + t;
                float s4[4] = {0.f, 0.f, 0.f, 0.f};
                uint32_t baddr = ksb + (uint32_t)((nf << 3) + (lane & 7)) * 144 + kboff;
#pragma unroll
                for (int kc = 0; kc < 4; kc++) {
                    uint32_t b0, b1;
                    ldmx2(b0, b1, baddr + kc * 32);
                    mma16h(s4, qf[kc][0], qf[kc][1], qf[kc][2], qf[kc][3], b0, b1);
                }
                float p0 = __expf(s4[0] * SCALE);
                float p1 = __expf(s4[1] * SCALE);
                float p2 = __expf(s4[2] * SCALE);
                float p3 = __expf(s4[3] * SCALE);
                zl0 += p0 + p1;
                zl1 += p2 + p3;
                __half2 lo = __floats2half2_rn(p0, p1);
                __half2 hi = __floats2half2_rn(p2, p3);
                int col = j0 + (nf << 3) + ((lane & 3) << 1);
                Aout[(size_t)(i0 + r) * (NPT >> 1) + (col >> 1)]     = lo;
                Aout[(size_t)(i0 + r + 8) * (NPT >> 1) + (col >> 1)] = hi;
                if (t == 0) { pe0 = *(uint32_t*)&lo; pe1 = *(uint32_t*)&hi; }
                else        { po0 = *(uint32_t*)&lo; po1 = *(uint32_t*)&hi; }
            }
            uint32_t rowaddr = vsb + (uint32_t)((ks << 4) + (lane & 15)) * 144;
#pragma unroll
            for (int nf2 = 0; nf2 < 8; nf2++) {
                uint32_t b0, b1;
                ldmx2t(b0, b1, rowaddr + (nf2 << 4));
                mma16h(oacc[nf2], pe0, pe1, po0, po1, b0, b1);
            }
        }
    }

    zl0 += __shfl_xor_sync(0xffffffffu, zl0, 1);
    zl0 += __shfl_xor_sync(0xffffffffu, zl0, 2);
    zl1 += __shfl_xor_sync(0xffffffffu, zl1, 1);
    zl1 += __shfl_xor_sync(0xffffffffu, zl1, 2);
    float iz0 = 1.0f / zl0, iz1 = 1.0f / zl1;
    if ((lane & 3) == 0) {
        g_Z[(size_t)hb * NPT + i0 + r]     = iz0;
        g_Z[(size_t)hb * NPT + i0 + r + 8] = iz1;
    }

    __half2* Oh = (__half2*)g_oh;
#pragma unroll
    for (int nf = 0; nf < 8; nf++) {
        int d = (nf << 3) + ((lane & 3) << 1);
        size_t gi0 = (size_t)(b * NPT + i0 + r) * DD + h * DH + d;
        size_t gi1 = gi0 + (size_t)8 * DD;
        float2 q0 = *(const float2*)(g_q + gi0);
        float2 q1 = *(const float2*)(g_q + gi1);
        float2 o0 = make_float2(q0.x + oacc[nf][0] * iz0, q0.y + oacc[nf][1] * iz0);
        float2 o1 = make_float2(q1.x + oacc[nf][2] * iz1, q1.y + oacc[nf][3] * iz1);
        *(float2*)(g_o + gi0) = o0;
        *(float2*)(g_o + gi1) = o1;
        Oh[gi0 >> 1] = __floats2half2_rn(o0.x, o0.y);
        Oh[gi1 >> 1] = __floats2half2_rn(o1.x, o1.y);
    }
}

// ======================================================================
// Am[b, j, i] = (1/8) * sum_h U[h,b,i,j] * invZ[h,b,i]   (half2 reads)
// ======================================================================
__global__ void __launch_bounds__(256) meanA_kernel(float* __restrict__ out)
{
    __shared__ float s[64][33];
    __shared__ float ziv[8][32];
    const int b  = blockIdx.z;
    const int i0 = blockIdx.x << 5;
    const int j0 = blockIdx.y << 6;
    const int tx = threadIdx.x & 31;
    const int ty = threadIdx.x >> 5;

    ziv[ty][tx] = g_Z[(size_t)(ty * NB + b) * NPT + i0 + tx];
    __syncthreads();

    float2 acc[4];
#pragma unroll
    for (int r = 0; r < 4; r++) acc[r] = make_float2(0.f, 0.f);

#pragma unroll
    for (int h = 0; h < 8; h++) {
        const __half2* base = (const __half2*)(
            g_A + ((size_t)(h * NB + b) * NPT + i0) * NPT + j0);
#pragma unroll
        for (int r = 0; r < 4; r++) {
            int ii = ty + (r << 3);
            float2 f = __half22float2(base[(size_t)ii * (NPT >> 1) + tx]);
            float z = ziv[h][ii];
            acc[r].x += f.x * z;
            acc[r].y += f.y * z;
        }
    }
#pragma unroll
    for (int r = 0; r < 4; r++) {
        int ii = ty + (r << 3);
        s[2 * tx][ii]     = acc[r].x * 0.125f;
        s[2 * tx + 1][ii] = acc[r].y * 0.125f;
    }
    __syncthreads();

    float* ob = out + ((size_t)b * NPT + j0) * NPT + i0;
#pragma unroll
    for (int rr = 0; rr < 8; rr++) {
        int jj = ty + (rr << 3);
        ob[(size_t)jj * NPT + tx] = s[jj][tx];
    }
}

// ======================================================================
// Launch
// ======================================================================
extern "C" void kernel_launch(void* const* d_in, const int* in_sizes, int n_in,
                              void* d_out, int out_size)
{
    const float* Q  = (const float*)d_in[0];
    const float* K  = (const float*)d_in[1];
    const float* Wq = (const float*)d_in[2];
    const float* bq = (const float*)d_in[3];
    const float* Wk = (const float*)d_in[4];
    const float* bk = (const float*)d_in[5];
    const float* Wv = (const float*)d_in[6];
    const float* bv = (const float*)d_in[7];
    const float* Wo = (const float*)d_in[8];
    const float* bo = (const float*)d_in[9];
    float* out = (float*)d_out;

    static bool init = false;
    static float *pq, *po;
    static __half *pqh, *pkh, *pvh, *poh, *pQin, *pKin, *pW;
    if (!init) {
        void* t;
        cudaGetSymbolAddress(&t, g_q);   pq   = (float*)t;
        cudaGetSymbolAddress(&t, g_o);   po   = (float*)t;
        cudaGetSymbolAddress(&t, g_qh);  pqh  = (__half*)t;
        cudaGetSymbolAddress(&t, g_kh);  pkh  = (__half*)t;
        cudaGetSymbolAddress(&t, g_vh);  pvh  = (__half*)t;
        cudaGetSymbolAddress(&t, g_oh);  poh  = (__half*)t;
        cudaGetSymbolAddress(&t, g_Qin); pQin = (__half*)t;
        cudaGetSymbolAddress(&t, g_Kin); pKin = (__half*)t;
        cudaGetSymbolAddress(&t, g_Wh);  pW   = (__half*)t;
        cudaFuncSetAttribute(fused_attn, cudaFuncAttributeMaxDynamicSharedMemorySize,
                             FUSED_SMEM_BYTES);
        cudaFuncSetAttribute(gemm512_h2<1>, cudaFuncAttributeMaxDynamicSharedMemorySize,
                             GEMM_SMEM_BYTES);
        cudaFuncSetAttribute(gemm512_h2<4>, cudaFuncAttributeMaxDynamicSharedMemorySize,
                             GEMM_SMEM_BYTES);
        cudaFuncSetAttribute(gemm512_h2<5>, cudaFuncAttributeMaxDynamicSharedMemorySize,
                             GEMM_SMEM_BYTES);
        init = true;
    }

    const size_t WSZ = (size_t)DD * DD;
    dim3 ggemm(DD / 64, MM / 128);                    // (8, 64)

    cvt_qk<<<dim3(1024, 2), 256>>>(Q, K);
    cvt_w<<<dim3(64, 4), 256>>>(Wq, Wk, Wv, Wo);

    gemm512_h2<5><<<ggemm, 256, GEMM_SMEM_BYTES>>>(pQin, pW + 0 * WSZ, bq, pq, (float*)pqh, nullptr);
    gemm512_h2<4><<<ggemm, 256, GEMM_SMEM_BYTES>>>(pKin, pW + 1 * WSZ, bk, (float*)pkh, nullptr, nullptr);
    gemm512_h2<4><<<ggemm, 256, GEMM_SMEM_BYTES>>>(pKin, pW + 2 * WSZ, bv, (float*)pvh, nullptr, nullptr);

    fused_attn<<<dim3(8, 64), 256, FUSED_SMEM_BYTES>>>();

    gemm512_h2<1><<<ggemm, 256, GEMM_SMEM_BYTES>>>(poh, pW + 3 * WSZ, bo, out, nullptr, po);
    meanA_kernel<<<dim3(32, 16, 8), 256>>>(out + (size_t)MM * DD);
}

// round 11
// speedup vs baseline: 2.2381x; 1.0617x over previous
#include <cuda_runtime.h>
#include <cuda_fp16.h>
#include <cstdint>

#define NB  8
#define NPT 1024
#define DD  512
#define NH  8
#define DH  64
#define MM  (NB * NPT)
#define SCALE 0.04419417382415922f   // 1/sqrt(512)

// ---------------- scratch (device globals; allocation-free) ----------------
__device__ float  g_q  [(size_t)MM * DD];            // fp32 q (exact residual)
__device__ __half g_qh [(size_t)MM * DD];            // fp16 q
__device__ __half g_kh [(size_t)MM * DD];            // fp16 k
__device__ __half g_vh [(size_t)MM * DD];            // fp16 v
__device__ float  g_o  [(size_t)MM * DD];            // fp32 O (residual for out-proj)
__device__ __half g_oh [(size_t)MM * DD];            // fp16 O (mma operand)
__device__ __half g_Qin[(size_t)MM * DD];            // fp16 raw Q
__device__ __half g_Kin[(size_t)MM * DD];            // fp16 raw K
__device__ __half g_Wh [4][(size_t)DD * DD];         // fp16 Wq,Wk,Wv,Wo
__device__ __half g_A  [(size_t)NH * NB * NPT * NPT];// U = exp(s), fp16
__device__ float  g_Z  [(size_t)NH * NB * NPT];      // 1/rowsum

// ---------------- helpers ----------------
__device__ __forceinline__ void mma16h(float* c, uint32_t a0, uint32_t a1,
                                       uint32_t a2, uint32_t a3,
                                       uint32_t b0, uint32_t b1) {
    asm volatile(
        "mma.sync.aligned.m16n8k16.row.col.f32.f16.f16.f32 "
        "{%0,%1,%2,%3},{%4,%5,%6,%7},{%8,%9},{%0,%1,%2,%3};"
        : "+f"(c[0]), "+f"(c[1]), "+f"(c[2]), "+f"(c[3])
        : "r"(a0), "r"(a1), "r"(a2), "r"(a3), "r"(b0), "r"(b1));
}
__device__ __forceinline__ void ldmx4(uint32_t& a0, uint32_t& a1, uint32_t& a2,
                                      uint32_t& a3, uint32_t addr) {
    asm volatile("ldmatrix.sync.aligned.m8n8.x4.shared.b16 {%0,%1,%2,%3}, [%4];"
                 : "=r"(a0), "=r"(a1), "=r"(a2), "=r"(a3) : "r"(addr));
}
__device__ __forceinline__ void ldmx2(uint32_t& b0, uint32_t& b1, uint32_t addr) {
    asm volatile("ldmatrix.sync.aligned.m8n8.x2.shared.b16 {%0,%1}, [%2];"
                 : "=r"(b0), "=r"(b1) : "r"(addr));
}
__device__ __forceinline__ void ldmx2t(uint32_t& b0, uint32_t& b1, uint32_t addr) {
    asm volatile("ldmatrix.sync.aligned.m8n8.x2.trans.shared.b16 {%0,%1}, [%2];"
                 : "=r"(b0), "=r"(b1) : "r"(addr));
}
__device__ __forceinline__ void cpa16(uint32_t dst, const void* src) {
    asm volatile("cp.async.cg.shared.global [%0], [%1], 16;" :: "r"(dst), "l"(src));
}
#define CP_COMMIT() asm volatile("cp.async.commit_group;")
#define CP_WAIT(N)  asm volatile("cp.async.wait_group %0;" :: "n"(N))

// ======================================================================
// fp32 -> fp16 conversion, single launch. grid (1024, 6)
// job 0: Q (16MB)  job 1: K  jobs 2..5: Wq,Wk,Wv,Wo (1MB each, x<64)
// ======================================================================
__global__ void __launch_bounds__(256) cvt_all(
    const float* __restrict__ Q, const float* __restrict__ K,
    const float* __restrict__ W0, const float* __restrict__ W1,
    const float* __restrict__ W2, const float* __restrict__ W3)
{
    const int job = blockIdx.y;
    if (job >= 2) {
        if (blockIdx.x >= 64) return;
        const float* ws[4] = {W0, W1, W2, W3};
        const float4* src = (const float4*)ws[job - 2];
        __half2* dst = (__half2*)g_Wh[job - 2];
        int i = blockIdx.x * 256 + threadIdx.x;
#pragma unroll
        for (int t = 0; t < 4; t++) {
            int idx = i + t * (64 * 256);
            float4 v = src[idx];
            dst[2 * idx]     = __floats2half2_rn(v.x, v.y);
            dst[2 * idx + 1] = __floats2half2_rn(v.z, v.w);
        }
        return;
    }
    const float4* src = (const float4*)(job ? K : Q);
    __half2* dst = (__half2*)(job ? g_Kin : g_Qin);
    int i = blockIdx.x * 256 + threadIdx.x;
#pragma unroll
    for (int t = 0; t < 4; t++) {
        int idx = i + t * (1024 * 256);
        float4 v = src[idx];
        dst[2 * idx]     = __floats2half2_rn(v.x, v.y);
        dst[2 * idx + 1] = __floats2half2_rn(v.z, v.w);
    }
}

// ======================================================================
// GEMM core (proven R9): fp16 operands via cp.async double-buffer,
// K-chunk 64, block 128x64, 8 warps 32x32, m16n8k16.
// smem bytes: Xs[2] 128x72h | Ws[2] 64x72h = 55296
// ======================================================================
#define GX_B(bu) ((bu) * 18432)
#define GW_B(bu) (36864 + (bu) * 9216)
#define GEMM_SMEM_BYTES 55296

struct GemmAcc { float a[2][4][4]; };

__device__ __forceinline__ void gemm_core(
    const __half* __restrict__ Xh, const __half* __restrict__ Wh,
    uint32_t sbase, int m0, int n0, int wm, int wn,
    int tid, int lane, GemmAcc& A)
{
#pragma unroll
    for (int mf = 0; mf < 2; mf++)
#pragma unroll
        for (int nf = 0; nf < 4; nf++)
#pragma unroll
            for (int x = 0; x < 4; x++) A.a[mf][nf][x] = 0.f;

    {
#pragma unroll
        for (int t = 0; t < 4; t++) {
            int c = tid + (t << 8);
            int rr = c >> 3, seg = c & 7;
            cpa16(sbase + GX_B(0) + rr * 144 + seg * 16,
                  (const char*)(Xh + (size_t)(m0 + rr) * DD) + seg * 16);
        }
#pragma unroll
        for (int t = 0; t < 2; t++) {
            int c = tid + (t << 8);
            int rr = c >> 3, seg = c & 7;
            cpa16(sbase + GW_B(0) + rr * 144 + seg * 16,
                  (const char*)(Wh + (size_t)rr * DD + n0) + seg * 16);
        }
        CP_COMMIT();
    }

    const uint32_t arow = (uint32_t)((lane & 7) + (((lane >> 3) & 1) << 3));
    const uint32_t akoff = ((lane >> 4) & 1) << 4;
    const uint32_t brow = (uint32_t)(lane & 15);

    for (int kc64 = 0; kc64 < 8; kc64++) {
        const int cur = kc64 & 1;
        const uint32_t xsb = sbase + GX_B(cur);
        const uint32_t wsb = sbase + GW_B(cur);

        CP_WAIT(0);
        __syncthreads();

        if (kc64 + 1 < 8) {
            const int nb = cur ^ 1;
            const int k0 = (kc64 + 1) << 6;
#pragma unroll
            for (int t = 0; t < 4; t++) {
                int c = tid + (t << 8);
                int rr = c >> 3, seg = c & 7;
                cpa16(sbase + GX_B(nb) + rr * 144 + seg * 16,
                      (const char*)(Xh + (size_t)(m0 + rr) * DD + k0) + seg * 16);
            }
#pragma unroll
            for (int t = 0; t < 2; t++) {
                int c = tid + (t << 8);
                int rr = c >> 3, seg = c & 7;
                cpa16(sbase + GW_B(nb) + rr * 144 + seg * 16,
                      (const char*)(Wh + (size_t)(k0 + rr) * DD + n0) + seg * 16);
            }
            CP_COMMIT();
        }

#pragma unroll
        for (int kc = 0; kc < 4; kc++) {
            uint32_t af[2][4];
#pragma unroll
            for (int mf = 0; mf < 2; mf++)
                ldmx4(af[mf][0], af[mf][1], af[mf][2], af[mf][3],
                      xsb + (uint32_t)(wm + (mf << 4) + arow) * 144 + akoff + kc * 32);
#pragma unroll
            for (int nf = 0; nf < 4; nf++) {
                uint32_t b0, b1;
                ldmx2t(b0, b1, wsb + ((kc << 4) + brow) * 144 + wn * 2 + (nf << 4));
#pragma unroll
                for (int mf = 0; mf < 2; mf++)
                    mma16h(A.a[mf][nf], af[mf][0], af[mf][1], af[mf][2], af[mf][3], b0, b1);
            }
        }
    }
}

extern __shared__ uint32_t gsm[];

// ---- merged projection GEMM: grid (8, 64, 3); z: 0=q, 1=k, 2=v ----
__global__ void __launch_bounds__(256, 2) proj3(
    const float* __restrict__ bq, const float* __restrict__ bk,
    const float* __restrict__ bv)
{
    const uint32_t sbase = (uint32_t)__cvta_generic_to_shared(gsm);
    const int tid = threadIdx.x, lane = tid & 31, w = tid >> 5;
    const int m0 = blockIdx.y << 7, n0 = blockIdx.x << 6;
    const int wm = (w & 3) << 5, wn = (w >> 2) << 5;
    const int z = blockIdx.z;

    const __half* Xh = (z == 0) ? g_Qin : g_Kin;
    const __half* Wh = g_Wh[z];
    const float* bias = (z == 0) ? bq : (z == 1) ? bk : bv;

    GemmAcc A;
    gemm_core(Xh, Wh, sbase, m0, n0, wm, wn, tid, lane, A);

    __half2* Ch = (__half2*)((z == 0) ? g_qh : (z == 1) ? g_kh : g_vh);
#pragma unroll
    for (int mf = 0; mf < 2; mf++) {
        int row = m0 + wm + (mf << 4) + (lane >> 2);
#pragma unroll
        for (int nf = 0; nf < 4; nf++) {
            int col = n0 + wn + (nf << 3) + ((lane & 3) << 1);
            float2 bb = *(const float2*)(bias + col);
            float2 v0 = make_float2(A.a[mf][nf][0] + bb.x, A.a[mf][nf][1] + bb.y);
            float2 v1 = make_float2(A.a[mf][nf][2] + bb.x, A.a[mf][nf][3] + bb.y);
            Ch[(size_t)row * (DD / 2) + (col >> 1)]       = __floats2half2_rn(v0.x, v0.y);
            Ch[(size_t)(row + 8) * (DD / 2) + (col >> 1)] = __floats2half2_rn(v1.x, v1.y);
            if (z == 0) {
                *(float2*)(g_q + (size_t)row * DD + col) = v0;
                *(float2*)(g_q + (size_t)(row + 8) * DD + col) = v1;
            }
        }
    }
}

// ---- out-projection: C = R + relu(O@Wo + bo) ----
__global__ void __launch_bounds__(256, 2) outproj(
    const float* __restrict__ bo, float* __restrict__ C)
{
    const uint32_t sbase = (uint32_t)__cvta_generic_to_shared(gsm);
    const int tid = threadIdx.x, lane = tid & 31, w = tid >> 5;
    const int m0 = blockIdx.y << 7, n0 = blockIdx.x << 6;
    const int wm = (w & 3) << 5, wn = (w >> 2) << 5;

    GemmAcc A;
    gemm_core(g_oh, g_Wh[3], sbase, m0, n0, wm, wn, tid, lane, A);

#pragma unroll
    for (int mf = 0; mf < 2; mf++) {
        int row = m0 + wm + (mf << 4) + (lane >> 2);
#pragma unroll
        for (int nf = 0; nf < 4; nf++) {
            int col = n0 + wn + (nf << 3) + ((lane & 3) << 1);
            float2 bb = *(const float2*)(bo + col);
            float2 v0 = make_float2(A.a[mf][nf][0] + bb.x, A.a[mf][nf][1] + bb.y);
            float2 v1 = make_float2(A.a[mf][nf][2] + bb.x, A.a[mf][nf][3] + bb.y);
            float2 r0 = *(const float2*)(g_o + (size_t)row * DD + col);
            float2 r1 = *(const float2*)(g_o + (size_t)(row + 8) * DD + col);
            v0.x = r0.x + fmaxf(v0.x, 0.f); v0.y = r0.y + fmaxf(v0.y, 0.f);
            v1.x = r1.x + fmaxf(v1.x, 0.f); v1.y = r1.y + fmaxf(v1.y, 0.f);
            *(float2*)(C + (size_t)row * DD + col) = v0;
            *(float2*)(C + (size_t)(row + 8) * DD + col) = v1;
        }
    }
}

// ======================================================================
// Fused attention v4: 4 warps x 16 i-rows (i-tile 64), grid (16, 64),
// 128 threads, 4 CTAs/SM. Same per-warp pipeline as R7-R9 (proven).
// smem: Qs 64x144B | Ks[2] 64x144B | Vs[2] 64x144B = 46080 B
// ======================================================================
#define QS_B 0
#define KS_B(bu) (9216 + (bu) * 9216)
#define VS_B(bu) (27648 + (bu) * 9216)
#define FUSED_SMEM_BYTES 46080

extern __shared__ uint32_t smw[];

__global__ void __launch_bounds__(128, 4) fused_attn()
{
    const uint32_t sbase = (uint32_t)__cvta_generic_to_shared(smw);

    const int tid = threadIdx.x, lane = tid & 31, wid = tid >> 5;
    const int hb = blockIdx.y, h = hb >> 3, b = hb & 7;
    const int i0 = blockIdx.x << 6;
    const int r = (wid << 4) + (lane >> 2);

    // cp.async Q tile (64 x 64 fp16): 512 chunks / 128 thr
    {
        const __half* src = g_qh + (size_t)(b * NPT + i0) * DD + h * DH;
#pragma unroll
        for (int t = 0; t < 4; t++) {
            int c = tid + (t << 7);
            int rr = c >> 3, seg = c & 7;
            cpa16(sbase + QS_B + rr * 144 + seg * 16,
                  (const char*)(src + (size_t)rr * DD) + seg * 16);
        }
        CP_COMMIT();
    }
    const __half* kbase = g_kh + (size_t)(b * NPT) * DD + h * DH;
    const __half* vbase = g_vh + (size_t)(b * NPT) * DD + h * DH;
#pragma unroll
    for (int t = 0; t < 4; t++) {
        int c = tid + (t << 7);
        int rr = c >> 3, seg = c & 7;
        cpa16(sbase + KS_B(0) + rr * 144 + seg * 16,
              (const char*)(kbase + (size_t)rr * DD) + seg * 16);
        cpa16(sbase + VS_B(0) + rr * 144 + seg * 16,
              (const char*)(vbase + (size_t)rr * DD) + seg * 16);
    }
    CP_COMMIT();

    uint32_t qf[4][4];
    CP_WAIT(1);
    __syncthreads();
    {
        const uint32_t qrow = (uint32_t)((wid << 4) + (lane & 7) + (((lane >> 3) & 1) << 3));
        const uint32_t koff = ((lane >> 4) & 1) << 4;
#pragma unroll
        for (int kc = 0; kc < 4; kc++)
            ldmx4(qf[kc][0], qf[kc][1], qf[kc][2], qf[kc][3],
                  sbase + QS_B + qrow * 144 + koff + kc * 32);
    }

    float oacc[8][4];
#pragma unroll
    for (int nf = 0; nf < 8; nf++)
#pragma unroll
        for (int x = 0; x < 4; x++) oacc[nf][x] = 0.f;
    float zl0 = 0.f, zl1 = 0.f;

    __half2* Aout = (__half2*)(g_A + (size_t)hb * NPT * NPT);

    for (int it = 0; it < 16; it++) {
        const int cur = it & 1;
        const uint32_t ksb = sbase + KS_B(cur);
        const uint32_t vsb = sbase + VS_B(cur);
        const int j0 = it << 6;

        CP_WAIT(0);
        __syncthreads();

        if (it + 1 < 16) {
            const int nb = cur ^ 1;
            const __half* kc = kbase + (size_t)(j0 + 64) * DD;
            const __half* vc = vbase + (size_t)(j0 + 64) * DD;
#pragma unroll
            for (int t = 0; t < 4; t++) {
                int c = tid + (t << 7);
                int rr = c >> 3, seg = c & 7;
                cpa16(sbase + KS_B(nb) + rr * 144 + seg * 16,
                      (const char*)(kc + (size_t)rr * DD) + seg * 16);
                cpa16(sbase + VS_B(nb) + rr * 144 + seg * 16,
                      (const char*)(vc + (size_t)rr * DD) + seg * 16);
            }
            CP_COMMIT();
        }

        const uint32_t kboff = (((lane >> 3) & 1) << 4);
#pragma unroll
        for (int ks = 0; ks < 4; ks++) {
            uint32_t pe0, pe1, po0, po1;
#pragma unroll
            for (int t = 0; t < 2; t++) {
                const int nf = (ks << 1) + t;
                float s4[4] = {0.f, 0.f, 0.f, 0.f};
                uint32_t baddr = ksb + (uint32_t)((nf << 3) + (lane & 7)) * 144 + kboff;
#pragma unroll
                for (int kc = 0; kc < 4; kc++) {
                    uint32_t b0, b1;
                    ldmx2(b0, b1, baddr + kc * 32);
                    mma16h(s4, qf[kc][0], qf[kc][1], qf[kc][2], qf[kc][3], b0, b1);
                }
                float p0 = __expf(s4[0] * SCALE);
                float p1 = __expf(s4[1] * SCALE);
                float p2 = __expf(s4[2] * SCALE);
                float p3 = __expf(s4[3] * SCALE);
                zl0 += p0 + p1;
                zl1 += p2 + p3;
                __half2 lo = __floats2half2_rn(p0, p1);
                __half2 hi = __floats2half2_rn(p2, p3);
                int col = j0 + (nf << 3) + ((lane & 3) << 1);
                Aout[(size_t)(i0 + r) * (NPT >> 1) + (col >> 1)]     = lo;
                Aout[(size_t)(i0 + r + 8) * (NPT >> 1) + (col >> 1)] = hi;
                if (t == 0) { pe0 = *(uint32_t*)&lo; pe1 = *(uint32_t*)&hi; }
                else        { po0 = *(uint32_t*)&lo; po1 = *(uint32_t*)&hi; }
            }
            uint32_t rowaddr = vsb + (uint32_t)((ks << 4) + (lane & 15)) * 144;
#pragma unroll
            for (int nf2 = 0; nf2 < 8; nf2++) {
                uint32_t b0, b1;
                ldmx2t(b0, b1, rowaddr + (nf2 << 4));
                mma16h(oacc[nf2], pe0, pe1, po0, po1, b0, b1);
            }
        }
    }

    zl0 += __shfl_xor_sync(0xffffffffu, zl0, 1);
    zl0 += __shfl_xor_sync(0xffffffffu, zl0, 2);
    zl1 += __shfl_xor_sync(0xffffffffu, zl1, 1);
    zl1 += __shfl_xor_sync(0xffffffffu, zl1, 2);
    float iz0 = 1.0f / zl0, iz1 = 1.0f / zl1;
    if ((lane & 3) == 0) {
        g_Z[(size_t)hb * NPT + i0 + r]     = iz0;
        g_Z[(size_t)hb * NPT + i0 + r + 8] = iz1;
    }

    __half2* Oh = (__half2*)g_oh;
#pragma unroll
    for (int nf = 0; nf < 8; nf++) {
        int d = (nf << 3) + ((lane & 3) << 1);
        size_t gi0 = (size_t)(b * NPT + i0 + r) * DD + h * DH + d;
        size_t gi1 = gi0 + (size_t)8 * DD;
        float2 q0 = *(const float2*)(g_q + gi0);
        float2 q1 = *(const float2*)(g_q + gi1);
        float2 o0 = make_float2(q0.x + oacc[nf][0] * iz0, q0.y + oacc[nf][1] * iz0);
        float2 o1 = make_float2(q1.x + oacc[nf][2] * iz1, q1.y + oacc[nf][3] * iz1);
        *(float2*)(g_o + gi0) = o0;
        *(float2*)(g_o + gi1) = o1;
        Oh[gi0 >> 1] = __floats2half2_rn(o0.x, o0.y);
        Oh[gi1 >> 1] = __floats2half2_rn(o1.x, o1.y);
    }
}

// ======================================================================
// Am[b, j, i] = (1/8) * sum_h U[h,b,i,j] * invZ[h,b,i]   (half2 reads)
// ======================================================================
__global__ void __launch_bounds__(256) meanA_kernel(float* __restrict__ out)
{
    __shared__ float s[64][33];
    __shared__ float ziv[8][32];
    const int b  = blockIdx.z;
    const int i0 = blockIdx.x << 5;
    const int j0 = blockIdx.y << 6;
    const int tx = threadIdx.x & 31;
    const int ty = threadIdx.x >> 5;

    ziv[ty][tx] = g_Z[(size_t)(ty * NB + b) * NPT + i0 + tx];
    __syncthreads();

    float2 acc[4];
#pragma unroll
    for (int r = 0; r < 4; r++) acc[r] = make_float2(0.f, 0.f);

#pragma unroll
    for (int h = 0; h < 8; h++) {
        const __half2* base = (const __half2*)(
            g_A + ((size_t)(h * NB + b) * NPT + i0) * NPT + j0);
#pragma unroll
        for (int r = 0; r < 4; r++) {
            int ii = ty + (r << 3);
            float2 f = __half22float2(base[(size_t)ii * (NPT >> 1) + tx]);
            float z = ziv[h][ii];
            acc[r].x += f.x * z;
            acc[r].y += f.y * z;
        }
    }
#pragma unroll
    for (int r = 0; r < 4; r++) {
        int ii = ty + (r << 3);
        s[2 * tx][ii]     = acc[r].x * 0.125f;
        s[2 * tx + 1][ii] = acc[r].y * 0.125f;
    }
    __syncthreads();

    float* ob = out + ((size_t)b * NPT + j0) * NPT + i0;
#pragma unroll
    for (int rr = 0; rr < 8; rr++) {
        int jj = ty + (rr << 3);
        ob[(size_t)jj * NPT + tx] = s[jj][tx];
    }
}

// ======================================================================
// Launch
// ======================================================================
extern "C" void kernel_launch(void* const* d_in, const int* in_sizes, int n_in,
                              void* d_out, int out_size)
{
    const float* Q  = (const float*)d_in[0];
    const float* K  = (const float*)d_in[1];
    const float* Wq = (const float*)d_in[2];
    const float* bq = (const float*)d_in[3];
    const float* Wk = (const float*)d_in[4];
    const float* bk = (const float*)d_in[5];
    const float* Wv = (const float*)d_in[6];
    const float* bv = (const float*)d_in[7];
    const float* Wo = (const float*)d_in[8];
    const float* bo = (const float*)d_in[9];
    float* out = (float*)d_out;

    static bool init = false;
    if (!init) {
        cudaFuncSetAttribute(fused_attn, cudaFuncAttributeMaxDynamicSharedMemorySize,
                             FUSED_SMEM_BYTES);
        cudaFuncSetAttribute(proj3, cudaFuncAttributeMaxDynamicSharedMemorySize,
                             GEMM_SMEM_BYTES);
        cudaFuncSetAttribute(outproj, cudaFuncAttributeMaxDynamicSharedMemorySize,
                             GEMM_SMEM_BYTES);
        init = true;
    }

    cvt_all<<<dim3(1024, 6), 256>>>(Q, K, Wq, Wk, Wv, Wo);

    proj3<<<dim3(8, 64, 3), 256, GEMM_SMEM_BYTES>>>(bq, bk, bv);

    fused_attn<<<dim3(16, 64), 128, FUSED_SMEM_BYTES>>>();

    outproj<<<dim3(8, 64), 256, GEMM_SMEM_BYTES>>>(bo, out);

    meanA_kernel<<<dim3(32, 16, 8), 256>>>(out + (size_t)MM * DD);
}

// round 12
// speedup vs baseline: 2.3073x; 1.0310x over previous
#include <cuda_runtime.h>
#include <cuda_fp16.h>
#include <cstdint>

#define NB  8
#define NPT 1024
#define DD  512
#define NH  8
#define DH  64
#define MM  (NB * NPT)
#define SCALE 0.04419417382415922f   // 1/sqrt(512)

// ---------------- scratch (device globals; allocation-free) ----------------
__device__ float  g_q  [(size_t)MM * DD];            // fp32 q (exact residual)
__device__ __half g_qh [(size_t)MM * DD];            // fp16 q
__device__ __half g_kh [(size_t)MM * DD];            // fp16 k
__device__ __half g_vh [(size_t)MM * DD];            // fp16 v
__device__ float  g_o  [(size_t)MM * DD];            // fp32 O (residual for out-proj)
__device__ __half g_oh [(size_t)MM * DD];            // fp16 O (mma operand)
__device__ __half g_Qin[(size_t)MM * DD];            // fp16 raw Q
__device__ __half g_Kin[(size_t)MM * DD];            // fp16 raw K
__device__ __half g_Wh [4][(size_t)DD * DD];         // fp16 Wq,Wk,Wv,Wo
__device__ __half g_A  [(size_t)NH * NB * NPT * NPT];// U = exp(s), fp16
__device__ float  g_Z  [(size_t)NH * NB * NPT];      // 1/rowsum

// ---------------- helpers ----------------
__device__ __forceinline__ void mma16h(float* c, uint32_t a0, uint32_t a1,
                                       uint32_t a2, uint32_t a3,
                                       uint32_t b0, uint32_t b1) {
    asm volatile(
        "mma.sync.aligned.m16n8k16.row.col.f32.f16.f16.f32 "
        "{%0,%1,%2,%3},{%4,%5,%6,%7},{%8,%9},{%0,%1,%2,%3};"
        : "+f"(c[0]), "+f"(c[1]), "+f"(c[2]), "+f"(c[3])
        : "r"(a0), "r"(a1), "r"(a2), "r"(a3), "r"(b0), "r"(b1));
}
__device__ __forceinline__ void ldmx4(uint32_t& a0, uint32_t& a1, uint32_t& a2,
                                      uint32_t& a3, uint32_t addr) {
    asm volatile("ldmatrix.sync.aligned.m8n8.x4.shared.b16 {%0,%1,%2,%3}, [%4];"
                 : "=r"(a0), "=r"(a1), "=r"(a2), "=r"(a3) : "r"(addr));
}
__device__ __forceinline__ void ldmx2(uint32_t& b0, uint32_t& b1, uint32_t addr) {
    asm volatile("ldmatrix.sync.aligned.m8n8.x2.shared.b16 {%0,%1}, [%2];"
                 : "=r"(b0), "=r"(b1) : "r"(addr));
}
__device__ __forceinline__ void ldmx2t(uint32_t& b0, uint32_t& b1, uint32_t addr) {
    asm volatile("ldmatrix.sync.aligned.m8n8.x2.trans.shared.b16 {%0,%1}, [%2];"
                 : "=r"(b0), "=r"(b1) : "r"(addr));
}
__device__ __forceinline__ void cpa16(uint32_t dst, const void* src) {
    asm volatile("cp.async.cg.shared.global [%0], [%1], 16;" :: "r"(dst), "l"(src));
}
#define CP_COMMIT() asm volatile("cp.async.commit_group;")
#define CP_WAIT(N)  asm volatile("cp.async.wait_group %0;" :: "n"(N))

// ======================================================================
// fp32 -> fp16 conversion, single launch. grid (1024, 2) + (64, 4 via y>=2)
// ======================================================================
__global__ void __launch_bounds__(256) cvt_all(
    const float* __restrict__ Q, const float* __restrict__ K,
    const float* __restrict__ W0, const float* __restrict__ W1,
    const float* __restrict__ W2, const float* __restrict__ W3)
{
    const int job = blockIdx.y;
    if (job >= 2) {
        if (blockIdx.x >= 64) return;
        const float* ws[4] = {W0, W1, W2, W3};
        const float4* src = (const float4*)ws[job - 2];
        __half2* dst = (__half2*)g_Wh[job - 2];
        int i = blockIdx.x * 256 + threadIdx.x;
#pragma unroll
        for (int t = 0; t < 4; t++) {
            int idx = i + t * (64 * 256);
            float4 v = src[idx];
            dst[2 * idx]     = __floats2half2_rn(v.x, v.y);
            dst[2 * idx + 1] = __floats2half2_rn(v.z, v.w);
        }
        return;
    }
    const float4* src = (const float4*)(job ? K : Q);
    __half2* dst = (__half2*)(job ? g_Kin : g_Qin);
    int i = blockIdx.x * 256 + threadIdx.x;
#pragma unroll
    for (int t = 0; t < 4; t++) {
        int idx = i + t * (1024 * 256);
        float4 v = src[idx];
        dst[2 * idx]     = __floats2half2_rn(v.x, v.y);
        dst[2 * idx + 1] = __floats2half2_rn(v.z, v.w);
    }
}

// ======================================================================
// GEMM core 64x64: fp16 operands via cp.async double-buffer, K-chunk 64.
// 128 threads = 4 warps (2x2), warp tile 32x32, m16n8k16, fp32 accum.
// smem bytes: Xs[2] 64x144B | Ws[2] 64x144B = 36864
// ======================================================================
#define GX_B(bu) ((bu) * 9216)
#define GW_B(bu) (18432 + (bu) * 9216)
#define GEMM_SMEM_BYTES 36864

struct GemmAcc { float a[2][4][4]; };

__device__ __forceinline__ void gemm_core64(
    const __half* __restrict__ Xh, const __half* __restrict__ Wh,
    uint32_t sbase, int m0, int n0, int wm, int wn,
    int tid, int lane, GemmAcc& A)
{
#pragma unroll
    for (int mf = 0; mf < 2; mf++)
#pragma unroll
        for (int nf = 0; nf < 4; nf++)
#pragma unroll
            for (int x = 0; x < 4; x++) A.a[mf][nf][x] = 0.f;

    {
#pragma unroll
        for (int t = 0; t < 4; t++) {
            int c = tid + (t << 7);
            int rr = c >> 3, seg = c & 7;
            cpa16(sbase + GX_B(0) + rr * 144 + seg * 16,
                  (const char*)(Xh + (size_t)(m0 + rr) * DD) + seg * 16);
            cpa16(sbase + GW_B(0) + rr * 144 + seg * 16,
                  (const char*)(Wh + (size_t)rr * DD + n0) + seg * 16);
        }
        CP_COMMIT();
    }

    const uint32_t arow = (uint32_t)((lane & 7) + (((lane >> 3) & 1) << 3));
    const uint32_t akoff = ((lane >> 4) & 1) << 4;
    const uint32_t brow = (uint32_t)(lane & 15);

    for (int kc64 = 0; kc64 < 8; kc64++) {
        const int cur = kc64 & 1;
        const uint32_t xsb = sbase + GX_B(cur);
        const uint32_t wsb = sbase + GW_B(cur);

        CP_WAIT(0);
        __syncthreads();

        if (kc64 + 1 < 8) {
            const int nb = cur ^ 1;
            const int k0 = (kc64 + 1) << 6;
#pragma unroll
            for (int t = 0; t < 4; t++) {
                int c = tid + (t << 7);
                int rr = c >> 3, seg = c & 7;
                cpa16(sbase + GX_B(nb) + rr * 144 + seg * 16,
                      (const char*)(Xh + (size_t)(m0 + rr) * DD + k0) + seg * 16);
                cpa16(sbase + GW_B(nb) + rr * 144 + seg * 16,
                      (const char*)(Wh + (size_t)(k0 + rr) * DD + n0) + seg * 16);
            }
            CP_COMMIT();
        }

#pragma unroll
        for (int kc = 0; kc < 4; kc++) {
            uint32_t af[2][4];
#pragma unroll
            for (int mf = 0; mf < 2; mf++)
                ldmx4(af[mf][0], af[mf][1], af[mf][2], af[mf][3],
                      xsb + (uint32_t)(wm + (mf << 4) + arow) * 144 + akoff + kc * 32);
#pragma unroll
            for (int nf = 0; nf < 4; nf++) {
                uint32_t b0, b1;
                ldmx2t(b0, b1, wsb + ((kc << 4) + brow) * 144 + wn * 2 + (nf << 4));
#pragma unroll
                for (int mf = 0; mf < 2; mf++)
                    mma16h(A.a[mf][nf], af[mf][0], af[mf][1], af[mf][2], af[mf][3], b0, b1);
            }
        }
    }
}

extern __shared__ uint32_t gsm[];

// ---- merged projection GEMM: grid (8, 128, 3); z: 0=q, 1=k, 2=v ----
__global__ void __launch_bounds__(128, 4) proj3(
    const float* __restrict__ bq, const float* __restrict__ bk,
    const float* __restrict__ bv)
{
    const uint32_t sbase = (uint32_t)__cvta_generic_to_shared(gsm);
    const int tid = threadIdx.x, lane = tid & 31, w = tid >> 5;
    const int m0 = blockIdx.y << 6, n0 = blockIdx.x << 6;
    const int wm = (w & 1) << 5, wn = (w >> 1) << 5;
    const int z = blockIdx.z;

    const __half* Xh = (z == 0) ? g_Qin : g_Kin;
    const __half* Wh = g_Wh[z];
    const float* bias = (z == 0) ? bq : (z == 1) ? bk : bv;

    GemmAcc A;
    gemm_core64(Xh, Wh, sbase, m0, n0, wm, wn, tid, lane, A);

    __half2* Ch = (__half2*)((z == 0) ? g_qh : (z == 1) ? g_kh : g_vh);
#pragma unroll
    for (int mf = 0; mf < 2; mf++) {
        int row = m0 + wm + (mf << 4) + (lane >> 2);
#pragma unroll
        for (int nf = 0; nf < 4; nf++) {
            int col = n0 + wn + (nf << 3) + ((lane & 3) << 1);
            float2 bb = *(const float2*)(bias + col);
            float2 v0 = make_float2(A.a[mf][nf][0] + bb.x, A.a[mf][nf][1] + bb.y);
            float2 v1 = make_float2(A.a[mf][nf][2] + bb.x, A.a[mf][nf][3] + bb.y);
            Ch[(size_t)row * (DD / 2) + (col >> 1)]       = __floats2half2_rn(v0.x, v0.y);
            Ch[(size_t)(row + 8) * (DD / 2) + (col >> 1)] = __floats2half2_rn(v1.x, v1.y);
            if (z == 0) {
                *(float2*)(g_q + (size_t)row * DD + col) = v0;
                *(float2*)(g_q + (size_t)(row + 8) * DD + col) = v1;
            }
        }
    }
}

// ---- out-projection: C = R + relu(O@Wo + bo), grid (8, 128) ----
__global__ void __launch_bounds__(128, 4) outproj(
    const float* __restrict__ bo, float* __restrict__ C)
{
    const uint32_t sbase = (uint32_t)__cvta_generic_to_shared(gsm);
    const int tid = threadIdx.x, lane = tid & 31, w = tid >> 5;
    const int m0 = blockIdx.y << 6, n0 = blockIdx.x << 6;
    const int wm = (w & 1) << 5, wn = (w >> 1) << 5;

    GemmAcc A;
    gemm_core64(g_oh, g_Wh[3], sbase, m0, n0, wm, wn, tid, lane, A);

#pragma unroll
    for (int mf = 0; mf < 2; mf++) {
        int row = m0 + wm + (mf << 4) + (lane >> 2);
#pragma unroll
        for (int nf = 0; nf < 4; nf++) {
            int col = n0 + wn + (nf << 3) + ((lane & 3) << 1);
            float2 bb = *(const float2*)(bo + col);
            float2 v0 = make_float2(A.a[mf][nf][0] + bb.x, A.a[mf][nf][1] + bb.y);
            float2 v1 = make_float2(A.a[mf][nf][2] + bb.x, A.a[mf][nf][3] + bb.y);
            float2 r0 = *(const float2*)(g_o + (size_t)row * DD + col);
            float2 r1 = *(const float2*)(g_o + (size_t)(row + 8) * DD + col);
            v0.x = r0.x + fmaxf(v0.x, 0.f); v0.y = r0.y + fmaxf(v0.y, 0.f);
            v1.x = r1.x + fmaxf(v1.x, 0.f); v1.y = r1.y + fmaxf(v1.y, 0.f);
            *(float2*)(C + (size_t)row * DD + col) = v0;
            *(float2*)(C + (size_t)(row + 8) * DD + col) = v1;
        }
    }
}

// ======================================================================
// Fused attention v4 (R10, proven): 4 warps x 16 i-rows, grid (16, 64),
// 128 threads, 4 CTAs/SM.
// smem: Qs 64x144B | Ks[2] 64x144B | Vs[2] 64x144B = 46080 B
// ======================================================================
#define QS_B 0
#define KS_B(bu) (9216 + (bu) * 9216)
#define VS_B(bu) (27648 + (bu) * 9216)
#define FUSED_SMEM_BYTES 46080

extern __shared__ uint32_t smw[];

__global__ void __launch_bounds__(128, 4) fused_attn()
{
    const uint32_t sbase = (uint32_t)__cvta_generic_to_shared(smw);

    const int tid = threadIdx.x, lane = tid & 31, wid = tid >> 5;
    const int hb = blockIdx.y, h = hb >> 3, b = hb & 7;
    const int i0 = blockIdx.x << 6;
    const int r = (wid << 4) + (lane >> 2);

    {
        const __half* src = g_qh + (size_t)(b * NPT + i0) * DD + h * DH;
#pragma unroll
        for (int t = 0; t < 4; t++) {
            int c = tid + (t << 7);
            int rr = c >> 3, seg = c & 7;
            cpa16(sbase + QS_B + rr * 144 + seg * 16,
                  (const char*)(src + (size_t)rr * DD) + seg * 16);
        }
        CP_COMMIT();
    }
    const __half* kbase = g_kh + (size_t)(b * NPT) * DD + h * DH;
    const __half* vbase = g_vh + (size_t)(b * NPT) * DD + h * DH;
#pragma unroll
    for (int t = 0; t < 4; t++) {
        int c = tid + (t << 7);
        int rr = c >> 3, seg = c & 7;
        cpa16(sbase + KS_B(0) + rr * 144 + seg * 16,
              (const char*)(kbase + (size_t)rr * DD) + seg * 16);
        cpa16(sbase + VS_B(0) + rr * 144 + seg * 16,
              (const char*)(vbase + (size_t)rr * DD) + seg * 16);
    }
    CP_COMMIT();

    uint32_t qf[4][4];
    CP_WAIT(1);
    __syncthreads();
    {
        const uint32_t qrow = (uint32_t)((wid << 4) + (lane & 7) + (((lane >> 3) & 1) << 3));
        const uint32_t koff = ((lane >> 4) & 1) << 4;
#pragma unroll
        for (int kc = 0; kc < 4; kc++)
            ldmx4(qf[kc][0], qf[kc][1], qf[kc][2], qf[kc][3],
                  sbase + QS_B + qrow * 144 + koff + kc * 32);
    }

    float oacc[8][4];
#pragma unroll
    for (int nf = 0; nf < 8; nf++)
#pragma unroll
        for (int x = 0; x < 4; x++) oacc[nf][x] = 0.f;
    float zl0 = 0.f, zl1 = 0.f;

    __half2* Aout = (__half2*)(g_A + (size_t)hb * NPT * NPT);

    for (int it = 0; it < 16; it++) {
        const int cur = it & 1;
        const uint32_t ksb = sbase + KS_B(cur);
        const uint32_t vsb = sbase + VS_B(cur);
        const int j0 = it << 6;

        CP_WAIT(0);
        __syncthreads();

        if (it + 1 < 16) {
            const int nb = cur ^ 1;
            const __half* kc = kbase + (size_t)(j0 + 64) * DD;
            const __half* vc = vbase + (size_t)(j0 + 64) * DD;
#pragma unroll
            for (int t = 0; t < 4; t++) {
                int c = tid + (t << 7);
                int rr = c >> 3, seg = c & 7;
                cpa16(sbase + KS_B(nb) + rr * 144 + seg * 16,
                      (const char*)(kc + (size_t)rr * DD) + seg * 16);
                cpa16(sbase + VS_B(nb) + rr * 144 + seg * 16,
                      (const char*)(vc + (size_t)rr * DD) + seg * 16);
            }
            CP_COMMIT();
        }

        const uint32_t kboff = (((lane >> 3) & 1) << 4);
#pragma unroll
        for (int ks = 0; ks < 4; ks++) {
            uint32_t pe0, pe1, po0, po1;
#pragma unroll
            for (int t = 0; t < 2; t++) {
                const int nf = (ks << 1) + t;
                float s4[4] = {0.f, 0.f, 0.f, 0.f};
                uint32_t baddr = ksb + (uint32_t)((nf << 3) + (lane & 7)) * 144 + kboff;
#pragma unroll
                for (int kc = 0; kc < 4; kc++) {
                    uint32_t b0, b1;
                    ldmx2(b0, b1, baddr + kc * 32);
                    mma16h(s4, qf[kc][0], qf[kc][1], qf[kc][2], qf[kc][3], b0, b1);
                }
                float p0 = __expf(s4[0] * SCALE);
                float p1 = __expf(s4[1] * SCALE);
                float p2 = __expf(s4[2] * SCALE);
                float p3 = __expf(s4[3] * SCALE);
                zl0 += p0 + p1;
                zl1 += p2 + p3;
                __half2 lo = __floats2half2_rn(p0, p1);
                __half2 hi = __floats2half2_rn(p2, p3);
                int col = j0 + (nf << 3) + ((lane & 3) << 1);
                Aout[(size_t)(i0 + r) * (NPT >> 1) + (col >> 1)]     = lo;
                Aout[(size_t)(i0 + r + 8) * (NPT >> 1) + (col >> 1)] = hi;
                if (t == 0) { pe0 = *(uint32_t*)&lo; pe1 = *(uint32_t*)&hi; }
                else        { po0 = *(uint32_t*)&lo; po1 = *(uint32_t*)&hi; }
            }
            uint32_t rowaddr = vsb + (uint32_t)((ks << 4) + (lane & 15)) * 144;
#pragma unroll
            for (int nf2 = 0; nf2 < 8; nf2++) {
                uint32_t b0, b1;
                ldmx2t(b0, b1, rowaddr + (nf2 << 4));
                mma16h(oacc[nf2], pe0, pe1, po0, po1, b0, b1);
            }
        }
    }

    zl0 += __shfl_xor_sync(0xffffffffu, zl0, 1);
    zl0 += __shfl_xor_sync(0xffffffffu, zl0, 2);
    zl1 += __shfl_xor_sync(0xffffffffu, zl1, 1);
    zl1 += __shfl_xor_sync(0xffffffffu, zl1, 2);
    float iz0 = 1.0f / zl0, iz1 = 1.0f / zl1;
    if ((lane & 3) == 0) {
        g_Z[(size_t)hb * NPT + i0 + r]     = iz0;
        g_Z[(size_t)hb * NPT + i0 + r + 8] = iz1;
    }

    __half2* Oh = (__half2*)g_oh;
#pragma unroll
    for (int nf = 0; nf < 8; nf++) {
        int d = (nf << 3) + ((lane & 3) << 1);
        size_t gi0 = (size_t)(b * NPT + i0 + r) * DD + h * DH + d;
        size_t gi1 = gi0 + (size_t)8 * DD;
        float2 q0 = *(const float2*)(g_q + gi0);
        float2 q1 = *(const float2*)(g_q + gi1);
        float2 o0 = make_float2(q0.x + oacc[nf][0] * iz0, q0.y + oacc[nf][1] * iz0);
        float2 o1 = make_float2(q1.x + oacc[nf][2] * iz1, q1.y + oacc[nf][3] * iz1);
        *(float2*)(g_o + gi0) = o0;
        *(float2*)(g_o + gi1) = o1;
        Oh[gi0 >> 1] = __floats2half2_rn(o0.x, o0.y);
        Oh[gi1 >> 1] = __floats2half2_rn(o1.x, o1.y);
    }
}

// ======================================================================
// Am[b, j, i] = (1/8) * sum_h U[h,b,i,j] * invZ[h,b,i]   (half2 reads)
// ======================================================================
__global__ void __launch_bounds__(256) meanA_kernel(float* __restrict__ out)
{
    __shared__ float s[64][33];
    __shared__ float ziv[8][32];
    const int b  = blockIdx.z;
    const int i0 = blockIdx.x << 5;
    const int j0 = blockIdx.y << 6;
    const int tx = threadIdx.x & 31;
    const int ty = threadIdx.x >> 5;

    ziv[ty][tx] = g_Z[(size_t)(ty * NB + b) * NPT + i0 + tx];
    __syncthreads();

    float2 acc[4];
#pragma unroll
    for (int r = 0; r < 4; r++) acc[r] = make_float2(0.f, 0.f);

#pragma unroll
    for (int h = 0; h < 8; h++) {
        const __half2* base = (const __half2*)(
            g_A + ((size_t)(h * NB + b) * NPT + i0) * NPT + j0);
#pragma unroll
        for (int r = 0; r < 4; r++) {
            int ii = ty + (r << 3);
            float2 f = __half22float2(base[(size_t)ii * (NPT >> 1) + tx]);
            float z = ziv[h][ii];
            acc[r].x += f.x * z;
            acc[r].y += f.y * z;
        }
    }
#pragma unroll
    for (int r = 0; r < 4; r++) {
        int ii = ty + (r << 3);
        s[2 * tx][ii]     = acc[r].x * 0.125f;
        s[2 * tx + 1][ii] = acc[r].y * 0.125f;
    }
    __syncthreads();

    float* ob = out + ((size_t)b * NPT + j0) * NPT + i0;
#pragma unroll
    for (int rr = 0; rr < 8; rr++) {
        int jj = ty + (rr << 3);
        ob[(size_t)jj * NPT + tx] = s[jj][tx];
    }
}

// ======================================================================
// Launch
// ======================================================================
extern "C" void kernel_launch(void* const* d_in, const int* in_sizes, int n_in,
                              void* d_out, int out_size)
{
    const float* Q  = (const float*)d_in[0];
    const float* K  = (const float*)d_in[1];
    const float* Wq = (const float*)d_in[2];
    const float* bq = (const float*)d_in[3];
    const float* Wk = (const float*)d_in[4];
    const float* bk = (const float*)d_in[5];
    const float* Wv = (const float*)d_in[6];
    const float* bv = (const float*)d_in[7];
    const float* Wo = (const float*)d_in[8];
    const float* bo = (const float*)d_in[9];
    float* out = (float*)d_out;

    static bool init = false;
    if (!init) {
        cudaFuncSetAttribute(fused_attn, cudaFuncAttributeMaxDynamicSharedMemorySize,
                             FUSED_SMEM_BYTES);
        cudaFuncSetAttribute(proj3, cudaFuncAttributeMaxDynamicSharedMemorySize,
                             GEMM_SMEM_BYTES);
        cudaFuncSetAttribute(outproj, cudaFuncAttributeMaxDynamicSharedMemorySize,
                             GEMM_SMEM_BYTES);
        init = true;
    }

    cvt_all<<<dim3(1024, 6), 256>>>(Q, K, Wq, Wk, Wv, Wo);

    proj3<<<dim3(8, 128, 3), 128, GEMM_SMEM_BYTES>>>(bq, bk, bv);

    fused_attn<<<dim3(16, 64), 128, FUSED_SMEM_BYTES>>>();

    outproj<<<dim3(8, 128), 128, GEMM_SMEM_BYTES>>>(bo, out);

    meanA_kernel<<<dim3(32, 16, 8), 256>>>(out + (size_t)MM * DD);
}

// round 13
// speedup vs baseline: 2.3450x; 1.0163x over previous
#include <cuda_runtime.h>
#include <cuda_fp16.h>
#include <cstdint>

#define NB  8
#define NPT 1024
#define DD  512
#define NH  8
#define DH  64
#define MM  (NB * NPT)
#define SCALE 0.04419417382415922f   // 1/sqrt(512)

// ---------------- scratch (device globals; allocation-free) ----------------
__device__ float  g_q  [(size_t)MM * DD];            // fp32 q (exact residual)
__device__ __half g_qh [(size_t)MM * DD];            // fp16 q
__device__ __half g_kh [(size_t)MM * DD];            // fp16 k
__device__ __half g_vh [(size_t)MM * DD];            // fp16 v
__device__ float  g_o  [(size_t)MM * DD];            // fp32 O (residual for out-proj)
__device__ __half g_oh [(size_t)MM * DD];            // fp16 O (mma operand)
__device__ __half g_Qin[(size_t)MM * DD];            // fp16 raw Q
__device__ __half g_Kin[(size_t)MM * DD];            // fp16 raw K
__device__ __half g_Wh [4][(size_t)DD * DD];         // fp16 Wq,Wk,Wv,Wo
__device__ __half g_A  [(size_t)NH * NB * NPT * NPT];// U = exp(s), fp16
__device__ float  g_Z  [(size_t)NH * NB * NPT];      // 1/rowsum

// ---------------- helpers ----------------
__device__ __forceinline__ void mma16h(float* c, uint32_t a0, uint32_t a1,
                                       uint32_t a2, uint32_t a3,
                                       uint32_t b0, uint32_t b1) {
    asm volatile(
        "mma.sync.aligned.m16n8k16.row.col.f32.f16.f16.f32 "
        "{%0,%1,%2,%3},{%4,%5,%6,%7},{%8,%9},{%0,%1,%2,%3};"
        : "+f"(c[0]), "+f"(c[1]), "+f"(c[2]), "+f"(c[3])
        : "r"(a0), "r"(a1), "r"(a2), "r"(a3), "r"(b0), "r"(b1));
}
__device__ __forceinline__ void ldmx4(uint32_t& a0, uint32_t& a1, uint32_t& a2,
                                      uint32_t& a3, uint32_t addr) {
    asm volatile("ldmatrix.sync.aligned.m8n8.x4.shared.b16 {%0,%1,%2,%3}, [%4];"
                 : "=r"(a0), "=r"(a1), "=r"(a2), "=r"(a3) : "r"(addr));
}
__device__ __forceinline__ void ldmx2(uint32_t& b0, uint32_t& b1, uint32_t addr) {
    asm volatile("ldmatrix.sync.aligned.m8n8.x2.shared.b16 {%0,%1}, [%2];"
                 : "=r"(b0), "=r"(b1) : "r"(addr));
}
__device__ __forceinline__ void ldmx2t(uint32_t& b0, uint32_t& b1, uint32_t addr) {
    asm volatile("ldmatrix.sync.aligned.m8n8.x2.trans.shared.b16 {%0,%1}, [%2];"
                 : "=r"(b0), "=r"(b1) : "r"(addr));
}
__device__ __forceinline__ void cpa16(uint32_t dst, const void* src) {
    asm volatile("cp.async.cg.shared.global [%0], [%1], 16;" :: "r"(dst), "l"(src));
}
#define CP_COMMIT() asm volatile("cp.async.commit_group;")
#define CP_WAIT(N)  asm volatile("cp.async.wait_group %0;" :: "n"(N))

// ======================================================================
// fp32 -> fp16 conversion, single launch.
// ======================================================================
__global__ void __launch_bounds__(256) cvt_all(
    const float* __restrict__ Q, const float* __restrict__ K,
    const float* __restrict__ W0, const float* __restrict__ W1,
    const float* __restrict__ W2, const float* __restrict__ W3)
{
    const int job = blockIdx.y;
    if (job >= 2) {
        if (blockIdx.x >= 64) return;
        const float* ws[4] = {W0, W1, W2, W3};
        const float4* src = (const float4*)ws[job - 2];
        __half2* dst = (__half2*)g_Wh[job - 2];
        int i = blockIdx.x * 256 + threadIdx.x;
#pragma unroll
        for (int t = 0; t < 4; t++) {
            int idx = i + t * (64 * 256);
            float4 v = src[idx];
            dst[2 * idx]     = __floats2half2_rn(v.x, v.y);
            dst[2 * idx + 1] = __floats2half2_rn(v.z, v.w);
        }
        return;
    }
    const float4* src = (const float4*)(job ? K : Q);
    __half2* dst = (__half2*)(job ? g_Kin : g_Qin);
    int i = blockIdx.x * 256 + threadIdx.x;
#pragma unroll
    for (int t = 0; t < 4; t++) {
        int idx = i + t * (1024 * 256);
        float4 v = src[idx];
        dst[2 * idx]     = __floats2half2_rn(v.x, v.y);
        dst[2 * idx + 1] = __floats2half2_rn(v.z, v.w);
    }
}

// ======================================================================
// GEMM core 64x64, 3-stage cp.async pipeline, K-chunk 64.
// 128 threads = 4 warps (2x2), warp tile 32x32, m16n8k16, fp32 accum.
// smem bytes: Xs[3] 64x144B | Ws[3] 64x144B = 55296
// ======================================================================
#define GX_B(bu) ((bu) * 9216)
#define GW_B(bu) (27648 + (bu) * 9216)
#define GEMM_SMEM_BYTES 55296

struct GemmAcc { float a[2][4][4]; };

__device__ __forceinline__ void gemm_stage_load(
    const __half* __restrict__ Xh, const __half* __restrict__ Wh,
    uint32_t sbase, int m0, int n0, int tid, int stage, int k0)
{
#pragma unroll
    for (int t = 0; t < 4; t++) {
        int c = tid + (t << 7);
        int rr = c >> 3, seg = c & 7;
        cpa16(sbase + GX_B(stage) + rr * 144 + seg * 16,
              (const char*)(Xh + (size_t)(m0 + rr) * DD + k0) + seg * 16);
        cpa16(sbase + GW_B(stage) + rr * 144 + seg * 16,
              (const char*)(Wh + (size_t)(k0 + rr) * DD + n0) + seg * 16);
    }
    CP_COMMIT();
}

__device__ __forceinline__ void gemm_core64(
    const __half* __restrict__ Xh, const __half* __restrict__ Wh,
    uint32_t sbase, int m0, int n0, int wm, int wn,
    int tid, int lane, GemmAcc& A)
{
#pragma unroll
    for (int mf = 0; mf < 2; mf++)
#pragma unroll
        for (int nf = 0; nf < 4; nf++)
#pragma unroll
            for (int x = 0; x < 4; x++) A.a[mf][nf][x] = 0.f;

    // prologue: stages 0, 1 in flight
    gemm_stage_load(Xh, Wh, sbase, m0, n0, tid, 0, 0);
    gemm_stage_load(Xh, Wh, sbase, m0, n0, tid, 1, 64);

    const uint32_t arow = (uint32_t)((lane & 7) + (((lane >> 3) & 1) << 3));
    const uint32_t akoff = ((lane >> 4) & 1) << 4;
    const uint32_t brow = (uint32_t)(lane & 15);

    int buf = 0;
    for (int kc64 = 0; kc64 < 8; kc64++) {
        if (kc64 < 7) { CP_WAIT(1); } else { CP_WAIT(0); }
        __syncthreads();

        const uint32_t xsb = sbase + GX_B(buf);
        const uint32_t wsb = sbase + GW_B(buf);

        if (kc64 + 2 < 8) {
            int nb = buf + 2; if (nb >= 3) nb -= 3;
            gemm_stage_load(Xh, Wh, sbase, m0, n0, tid, nb, (kc64 + 2) << 6);
        }

#pragma unroll
        for (int kc = 0; kc < 4; kc++) {
            uint32_t af[2][4];
#pragma unroll
            for (int mf = 0; mf < 2; mf++)
                ldmx4(af[mf][0], af[mf][1], af[mf][2], af[mf][3],
                      xsb + (uint32_t)(wm + (mf << 4) + arow) * 144 + akoff + kc * 32);
#pragma unroll
            for (int nf = 0; nf < 4; nf++) {
                uint32_t b0, b1;
                ldmx2t(b0, b1, wsb + ((kc << 4) + brow) * 144 + wn * 2 + (nf << 4));
#pragma unroll
                for (int mf = 0; mf < 2; mf++)
                    mma16h(A.a[mf][nf], af[mf][0], af[mf][1], af[mf][2], af[mf][3], b0, b1);
            }
        }
        if (++buf >= 3) buf = 0;
    }
}

extern __shared__ uint32_t gsm[];

// ---- merged projection GEMM: grid (8, 128, 3); z: 0=q, 1=k, 2=v ----
__global__ void __launch_bounds__(128, 4) proj3(
    const float* __restrict__ bq, const float* __restrict__ bk,
    const float* __restrict__ bv)
{
    const uint32_t sbase = (uint32_t)__cvta_generic_to_shared(gsm);
    const int tid = threadIdx.x, lane = tid & 31, w = tid >> 5;
    const int m0 = blockIdx.y << 6, n0 = blockIdx.x << 6;
    const int wm = (w & 1) << 5, wn = (w >> 1) << 5;
    const int z = blockIdx.z;

    const __half* Xh = (z == 0) ? g_Qin : g_Kin;
    const __half* Wh = g_Wh[z];
    const float* bias = (z == 0) ? bq : (z == 1) ? bk : bv;

    GemmAcc A;
    gemm_core64(Xh, Wh, sbase, m0, n0, wm, wn, tid, lane, A);

    __half2* Ch = (__half2*)((z == 0) ? g_qh : (z == 1) ? g_kh : g_vh);
#pragma unroll
    for (int mf = 0; mf < 2; mf++) {
        int row = m0 + wm + (mf << 4) + (lane >> 2);
#pragma unroll
        for (int nf = 0; nf < 4; nf++) {
            int col = n0 + wn + (nf << 3) + ((lane & 3) << 1);
            float2 bb = *(const float2*)(bias + col);
            float2 v0 = make_float2(A.a[mf][nf][0] + bb.x, A.a[mf][nf][1] + bb.y);
            float2 v1 = make_float2(A.a[mf][nf][2] + bb.x, A.a[mf][nf][3] + bb.y);
            Ch[(size_t)row * (DD / 2) + (col >> 1)]       = __floats2half2_rn(v0.x, v0.y);
            Ch[(size_t)(row + 8) * (DD / 2) + (col >> 1)] = __floats2half2_rn(v1.x, v1.y);
            if (z == 0) {
                *(float2*)(g_q + (size_t)row * DD + col) = v0;
                *(float2*)(g_q + (size_t)(row + 8) * DD + col) = v1;
            }
        }
    }
}

// ---- out-projection: C = R + relu(O@Wo + bo), grid (8, 128) ----
__global__ void __launch_bounds__(128, 4) outproj(
    const float* __restrict__ bo, float* __restrict__ C)
{
    const uint32_t sbase = (uint32_t)__cvta_generic_to_shared(gsm);
    const int tid = threadIdx.x, lane = tid & 31, w = tid >> 5;
    const int m0 = blockIdx.y << 6, n0 = blockIdx.x << 6;
    const int wm = (w & 1) << 5, wn = (w >> 1) << 5;

    GemmAcc A;
    gemm_core64(g_oh, g_Wh[3], sbase, m0, n0, wm, wn, tid, lane, A);

#pragma unroll
    for (int mf = 0; mf < 2; mf++) {
        int row = m0 + wm + (mf << 4) + (lane >> 2);
#pragma unroll
        for (int nf = 0; nf < 4; nf++) {
            int col = n0 + wn + (nf << 3) + ((lane & 3) << 1);
            float2 bb = *(const float2*)(bo + col);
            float2 v0 = make_float2(A.a[mf][nf][0] + bb.x, A.a[mf][nf][1] + bb.y);
            float2 v1 = make_float2(A.a[mf][nf][2] + bb.x, A.a[mf][nf][3] + bb.y);
            float2 r0 = *(const float2*)(g_o + (size_t)row * DD + col);
            float2 r1 = *(const float2*)(g_o + (size_t)(row + 8) * DD + col);
            v0.x = r0.x + fmaxf(v0.x, 0.f); v0.y = r0.y + fmaxf(v0.y, 0.f);
            v1.x = r1.x + fmaxf(v1.x, 0.f); v1.y = r1.y + fmaxf(v1.y, 0.f);
            *(float2*)(C + (size_t)row * DD + col) = v0;
            *(float2*)(C + (size_t)(row + 8) * DD + col) = v1;
        }
    }
}

// ======================================================================
// Fused attention v4 (R10/R11, proven): 4 warps x 16 i-rows, grid (16, 64),
// 128 threads, 4 CTAs/SM.
// ======================================================================
#define QS_B 0
#define KS_B(bu) (9216 + (bu) * 9216)
#define VS_B(bu) (27648 + (bu) * 9216)
#define FUSED_SMEM_BYTES 46080

extern __shared__ uint32_t smw[];

__global__ void __launch_bounds__(128, 4) fused_attn()
{
    const uint32_t sbase = (uint32_t)__cvta_generic_to_shared(smw);

    const int tid = threadIdx.x, lane = tid & 31, wid = tid >> 5;
    const int hb = blockIdx.y, h = hb >> 3, b = hb & 7;
    const int i0 = blockIdx.x << 6;
    const int r = (wid << 4) + (lane >> 2);

    {
        const __half* src = g_qh + (size_t)(b * NPT + i0) * DD + h * DH;
#pragma unroll
        for (int t = 0; t < 4; t++) {
            int c = tid + (t << 7);
            int rr = c >> 3, seg = c & 7;
            cpa16(sbase + QS_B + rr * 144 + seg * 16,
                  (const char*)(src + (size_t)rr * DD) + seg * 16);
        }
        CP_COMMIT();
    }
    const __half* kbase = g_kh + (size_t)(b * NPT) * DD + h * DH;
    const __half* vbase = g_vh + (size_t)(b * NPT) * DD + h * DH;
#pragma unroll
    for (int t = 0; t < 4; t++) {
        int c = tid + (t << 7);
        int rr = c >> 3, seg = c & 7;
        cpa16(sbase + KS_B(0) + rr * 144 + seg * 16,
              (const char*)(kbase + (size_t)rr * DD) + seg * 16);
        cpa16(sbase + VS_B(0) + rr * 144 + seg * 16,
              (const char*)(vbase + (size_t)rr * DD) + seg * 16);
    }
    CP_COMMIT();

    uint32_t qf[4][4];
    CP_WAIT(1);
    __syncthreads();
    {
        const uint32_t qrow = (uint32_t)((wid << 4) + (lane & 7) + (((lane >> 3) & 1) << 3));
        const uint32_t koff = ((lane >> 4) & 1) << 4;
#pragma unroll
        for (int kc = 0; kc < 4; kc++)
            ldmx4(qf[kc][0], qf[kc][1], qf[kc][2], qf[kc][3],
                  sbase + QS_B + qrow * 144 + koff + kc * 32);
    }

    float oacc[8][4];
#pragma unroll
    for (int nf = 0; nf < 8; nf++)
#pragma unroll
        for (int x = 0; x < 4; x++) oacc[nf][x] = 0.f;
    float zl0 = 0.f, zl1 = 0.f;

    __half2* Aout = (__half2*)(g_A + (size_t)hb * NPT * NPT);

    for (int it = 0; it < 16; it++) {
        const int cur = it & 1;
        const uint32_t ksb = sbase + KS_B(cur);
        const uint32_t vsb = sbase + VS_B(cur);
        const int j0 = it << 6;

        CP_WAIT(0);
        __syncthreads();

        if (it + 1 < 16) {
            const int nb = cur ^ 1;
            const __half* kc = kbase + (size_t)(j0 + 64) * DD;
            const __half* vc = vbase + (size_t)(j0 + 64) * DD;
#pragma unroll
            for (int t = 0; t < 4; t++) {
                int c = tid + (t << 7);
                int rr = c >> 3, seg = c & 7;
                cpa16(sbase + KS_B(nb) + rr * 144 + seg * 16,
                      (const char*)(kc + (size_t)rr * DD) + seg * 16);
                cpa16(sbase + VS_B(nb) + rr * 144 + seg * 16,
                      (const char*)(vc + (size_t)rr * DD) + seg * 16);
            }
            CP_COMMIT();
        }

        const uint32_t kboff = (((lane >> 3) & 1) << 4);
#pragma unroll
        for (int ks = 0; ks < 4; ks++) {
            uint32_t pe0, pe1, po0, po1;
#pragma unroll
            for (int t = 0; t < 2; t++) {
                const int nf = (ks << 1) + t;
                float s4[4] = {0.f, 0.f, 0.f, 0.f};
                uint32_t baddr = ksb + (uint32_t)((nf << 3) + (lane & 7)) * 144 + kboff;
#pragma unroll
                for (int kc = 0; kc < 4; kc++) {
                    uint32_t b0, b1;
                    ldmx2(b0, b1, baddr + kc * 32);
                    mma16h(s4, qf[kc][0], qf[kc][1], qf[kc][2], qf[kc][3], b0, b1);
                }
                float p0 = __expf(s4[0] * SCALE);
                float p1 = __expf(s4[1] * SCALE);
                float p2 = __expf(s4[2] * SCALE);
                float p3 = __expf(s4[3] * SCALE);
                zl0 += p0 + p1;
                zl1 += p2 + p3;
                __half2 lo = __floats2half2_rn(p0, p1);
                __half2 hi = __floats2half2_rn(p2, p3);
                int col = j0 + (nf << 3) + ((lane & 3) << 1);
                Aout[(size_t)(i0 + r) * (NPT >> 1) + (col >> 1)]     = lo;
                Aout[(size_t)(i0 + r + 8) * (NPT >> 1) + (col >> 1)] = hi;
                if (t == 0) { pe0 = *(uint32_t*)&lo; pe1 = *(uint32_t*)&hi; }
                else        { po0 = *(uint32_t*)&lo; po1 = *(uint32_t*)&hi; }
            }
            uint32_t rowaddr = vsb + (uint32_t)((ks << 4) + (lane & 15)) * 144;
#pragma unroll
            for (int nf2 = 0; nf2 < 8; nf2++) {
                uint32_t b0, b1;
                ldmx2t(b0, b1, rowaddr + (nf2 << 4));
                mma16h(oacc[nf2], pe0, pe1, po0, po1, b0, b1);
            }
        }
    }

    zl0 += __shfl_xor_sync(0xffffffffu, zl0, 1);
    zl0 += __shfl_xor_sync(0xffffffffu, zl0, 2);
    zl1 += __shfl_xor_sync(0xffffffffu, zl1, 1);
    zl1 += __shfl_xor_sync(0xffffffffu, zl1, 2);
    float iz0 = 1.0f / zl0, iz1 = 1.0f / zl1;
    if ((lane & 3) == 0) {
        g_Z[(size_t)hb * NPT + i0 + r]     = iz0;
        g_Z[(size_t)hb * NPT + i0 + r + 8] = iz1;
    }

    __half2* Oh = (__half2*)g_oh;
#pragma unroll
    for (int nf = 0; nf < 8; nf++) {
        int d = (nf << 3) + ((lane & 3) << 1);
        size_t gi0 = (size_t)(b * NPT + i0 + r) * DD + h * DH + d;
        size_t gi1 = gi0 + (size_t)8 * DD;
        float2 q0 = *(const float2*)(g_q + gi0);
        float2 q1 = *(const float2*)(g_q + gi1);
        float2 o0 = make_float2(q0.x + oacc[nf][0] * iz0, q0.y + oacc[nf][1] * iz0);
        float2 o1 = make_float2(q1.x + oacc[nf][2] * iz1, q1.y + oacc[nf][3] * iz1);
        *(float2*)(g_o + gi0) = o0;
        *(float2*)(g_o + gi1) = o1;
        Oh[gi0 >> 1] = __floats2half2_rn(o0.x, o0.y);
        Oh[gi1 >> 1] = __floats2half2_rn(o1.x, o1.y);
    }
}

// ======================================================================
// Am[b, j, i] = (1/8) * sum_h U[h,b,i,j] * invZ[h,b,i]   (half2 reads)
// ======================================================================
__global__ void __launch_bounds__(256) meanA_kernel(float* __restrict__ out)
{
    __shared__ float s[64][33];
    __shared__ float ziv[8][32];
    const int b  = blockIdx.z;
    const int i0 = blockIdx.x << 5;
    const int j0 = blockIdx.y << 6;
    const int tx = threadIdx.x & 31;
    const int ty = threadIdx.x >> 5;

    ziv[ty][tx] = g_Z[(size_t)(ty * NB + b) * NPT + i0 + tx];
    __syncthreads();

    float2 acc[4];
#pragma unroll
    for (int r = 0; r < 4; r++) acc[r] = make_float2(0.f, 0.f);

#pragma unroll
    for (int h = 0; h < 8; h++) {
        const __half2* base = (const __half2*)(
            g_A + ((size_t)(h * NB + b) * NPT + i0) * NPT + j0);
#pragma unroll
        for (int r = 0; r < 4; r++) {
            int ii = ty + (r << 3);
            float2 f = __half22float2(base[(size_t)ii * (NPT >> 1) + tx]);
            float z = ziv[h][ii];
            acc[r].x += f.x * z;
            acc[r].y += f.y * z;
        }
    }
#pragma unroll
    for (int r = 0; r < 4; r++) {
        int ii = ty + (r << 3);
        s[2 * tx][ii]     = acc[r].x * 0.125f;
        s[2 * tx + 1][ii] = acc[r].y * 0.125f;
    }
    __syncthreads();

    float* ob = out + ((size_t)b * NPT + j0) * NPT + i0;
#pragma unroll
    for (int rr = 0; rr < 8; rr++) {
        int jj = ty + (rr << 3);
        ob[(size_t)jj * NPT + tx] = s[jj][tx];
    }
}

// ======================================================================
// Launch — meanA forked onto a side stream, overlapping outproj.
// ======================================================================
extern "C" void kernel_launch(void* const* d_in, const int* in_sizes, int n_in,
                              void* d_out, int out_size)
{
    const float* Q  = (const float*)d_in[0];
    const float* K  = (const float*)d_in[1];
    const float* Wq = (const float*)d_in[2];
    const float* bq = (const float*)d_in[3];
    const float* Wk = (const float*)d_in[4];
    const float* bk = (const float*)d_in[5];
    const float* Wv = (const float*)d_in[6];
    const float* bv = (const float*)d_in[7];
    const float* Wo = (const float*)d_in[8];
    const float* bo = (const float*)d_in[9];
    float* out = (float*)d_out;

    static bool init = false;
    static cudaStream_t s2;
    static cudaEvent_t evFork, evJoin;
    if (!init) {
        cudaFuncSetAttribute(fused_attn, cudaFuncAttributeMaxDynamicSharedMemorySize,
                             FUSED_SMEM_BYTES);
        cudaFuncSetAttribute(proj3, cudaFuncAttributeMaxDynamicSharedMemorySize,
                             GEMM_SMEM_BYTES);
        cudaFuncSetAttribute(outproj, cudaFuncAttributeMaxDynamicSharedMemorySize,
                             GEMM_SMEM_BYTES);
        cudaStreamCreateWithFlags(&s2, cudaStreamNonBlocking);
        cudaEventCreateWithFlags(&evFork, cudaEventDisableTiming);
        cudaEventCreateWithFlags(&evJoin, cudaEventDisableTiming);
        init = true;
    }

    cvt_all<<<dim3(1024, 6), 256>>>(Q, K, Wq, Wk, Wv, Wo);

    proj3<<<dim3(8, 128, 3), 128, GEMM_SMEM_BYTES>>>(bq, bk, bv);

    fused_attn<<<dim3(16, 64), 128, FUSED_SMEM_BYTES>>>();

    // fork: meanA (reads g_A, g_Z) runs concurrently with outproj (reads g_oh, g_o)
    cudaEventRecord(evFork, 0);
    cudaStreamWaitEvent(s2, evFork, 0);
    meanA_kernel<<<dim3(32, 16, 8), 256, 0, s2>>>(out + (size_t)MM * DD);

    outproj<<<dim3(8, 128), 128, GEMM_SMEM_BYTES>>>(bo, out);

    // join
    cudaEventRecord(evJoin, s2);
    cudaStreamWaitEvent(0, evJoin, 0);
}